// round 1
// baseline (speedup 1.0000x reference)
#include <cuda_runtime.h>
#include <cuda_bf16.h>

// ---------------------------------------------------------------------------
// gameGAT fused kernel, fp32 + packed f32x2 FMA baseline.
// One CTA per batch element (16384 CTAs, 256 threads). All activations in
// shared memory; weights pre-packed (transposed, k-pair interleaved) into a
// __device__ arena by small prep kernels each launch.
// ---------------------------------------------------------------------------

#define RS 260            // activation row stride in floats (even, 8B-aligned rows)
#define NT 256            // threads per block
#define NNODES 23

// ---- arena layout (float offsets) ----
#define OFF_W1   0         // K=8(pad from 7), O=128 -> 1024
#define OFF_W2   1024      // 128x256 -> 32768
#define OFF_W3   33792     // 256x256 -> 65536
#define OFF_QW   99328
#define OFF_KW   164864
#define OFF_VW   230400
#define OFF_WQ   295936    // in_w rows 0..255, scaled by 1/sqrt(32)
#define OFF_WK   361472
#define OFF_WV   427008
#define OFF_OW   492544
#define OFF_O1   558080    // 256x128 -> 32768
#define OFF_O2   590848    // 128x64  -> 8192
#define OFF_O3   599040    // 64x2    -> 128
#define OFF_B1   599168
#define OFF_B2   599296
#define OFF_B3   599552
#define OFF_QB   599808
#define OFF_KB   600064
#define OFF_VB   600320
#define OFF_BQ   600576    // scaled
#define OFF_BK   600832
#define OFF_BV   601088
#define OFF_OB   601344
#define OFF_OB1  601600
#define OFF_OB2  601728
#define OFF_OB3  601792
#define ARENA_SZ 601856

__device__ float g_arena[ARENA_SZ];

// smem plan (floats):
// P0..P3 : 4 * 23*260 = 23920
// WT     : 16384   (weight tile double buffer / khT scratch)
// XS     : 184     (x padded to 23x8)
// POOL   : 256
// HD     : 192
#define SMEM_FLOATS (23920 + 16384 + 184 + 256 + 192)
#define SMEM_BYTES  (SMEM_FLOATS * 4)

__device__ __forceinline__ float2 ffma2(float2 a, float2 b, float2 c) {
    unsigned long long ua = reinterpret_cast<unsigned long long&>(a);
    unsigned long long ub = reinterpret_cast<unsigned long long&>(b);
    unsigned long long uc = reinterpret_cast<unsigned long long&>(c);
    unsigned long long ud;
    asm("fma.rn.f32x2 %0, %1, %2, %3;" : "=l"(ud) : "l"(ua), "l"(ub), "l"(uc));
    return reinterpret_cast<float2&>(ud);
}

// ---------------------------------------------------------------------------
// prep: pack weight [O][K] row-major -> arena [K/2][O] float2 (k-pair major)
// ---------------------------------------------------------------------------
__global__ void pack_weights(const float* __restrict__ src, int K, int O,
                             int Kpad, float scale, int dstOff) {
    int sz = (Kpad >> 1) * O * 2;
    for (int e = blockIdx.x * blockDim.x + threadIdx.x; e < sz;
         e += gridDim.x * blockDim.x) {
        int kp = e / (2 * O);
        int r  = e - kp * 2 * O;
        int j  = r >> 1;
        int t  = r & 1;
        int k  = 2 * kp + t;
        g_arena[dstOff + e] = (k < K) ? src[j * K + k] * scale : 0.f;
    }
}

__global__ void pack_biases(const float* b1, const float* b2, const float* b3,
                            const float* qb, const float* kb, const float* vb,
                            const float* inb, const float* ob,
                            const float* ob1, const float* ob2, const float* ob3) {
    const float s = 0.17677669529663687f;  // 1/sqrt(32)
    int t = threadIdx.x;
    for (int i = t; i < 128; i += NT) g_arena[OFF_B1 + i] = b1[i];
    for (int i = t; i < 256; i += NT) g_arena[OFF_B2 + i] = b2[i];
    for (int i = t; i < 256; i += NT) g_arena[OFF_B3 + i] = b3[i];
    for (int i = t; i < 256; i += NT) g_arena[OFF_QB + i] = qb[i];
    for (int i = t; i < 256; i += NT) g_arena[OFF_KB + i] = kb[i];
    for (int i = t; i < 256; i += NT) g_arena[OFF_VB + i] = vb[i];
    for (int i = t; i < 256; i += NT) g_arena[OFF_BQ + i] = inb[i] * s;
    for (int i = t; i < 256; i += NT) g_arena[OFF_BK + i] = inb[256 + i];
    for (int i = t; i < 256; i += NT) g_arena[OFF_BV + i] = inb[512 + i];
    for (int i = t; i < 256; i += NT) g_arena[OFF_OB + i] = ob[i];
    for (int i = t; i < 128; i += NT) g_arena[OFF_OB1 + i] = ob1[i];
    for (int i = t; i < 64;  i += NT) g_arena[OFF_OB2 + i] = ob2[i];
    for (int i = t; i < 2;   i += NT) g_arena[OFF_OB3 + i] = ob3[i];
}

// ---------------------------------------------------------------------------
// 23-row GEMM: Out[n][j] = act(bias[j] + sum_k In[n][k] * W[k][j])
// Weights packed [K/2][O] float2 in arena. Double-buffered smem tile, 32 k
// per tile. Thread j = output column. 23 float2 accumulators.
// ---------------------------------------------------------------------------
__device__ __forceinline__ void gemm23(const float* __restrict__ In, int istr,
                                       float* __restrict__ Out,
                                       int woff, int boff, int K, int O,
                                       bool act, float* WT, int tid) {
    const float2* Wg = reinterpret_cast<const float2*>(g_arena + woff);
    float2* WTb = reinterpret_cast<float2*>(WT);
    int npairs = K >> 1;
    int ntiles = (npairs + 15) >> 4;

    float2 acc[NNODES];
#pragma unroll
    for (int n = 0; n < NNODES; n++) acc[n] = make_float2(0.f, 0.f);

    {   // load tile 0 into buffer 0
        int cnt = min(16, npairs) * O;
        for (int idx = tid; idx < cnt; idx += NT) WTb[idx] = Wg[idx];
    }
    __syncthreads();

    for (int t = 0; t < ntiles; t++) {
        float2 r[16];
        int cntN = 0;
        if (t + 1 < ntiles) {                     // prefetch next tile -> regs
            int p0 = (t + 1) << 4;
            cntN = min(16, npairs - p0) * O;
            const float2* src = Wg + (size_t)p0 * O;
#pragma unroll
            for (int i = 0; i < 16; i++) {
                int idx = tid + (i << 8);
                if (idx < cntN) r[i] = src[idx];
            }
        }
        int pt = min(16, npairs - (t << 4));      // compute current tile
        if (tid < O) {
            const float2* Wt = WTb + (t & 1) * 4096;
            const float* Ik = In + (t << 5);
            for (int pp = 0; pp < pt; pp++) {
                float2 w = Wt[pp * O + tid];
#pragma unroll
                for (int n = 0; n < NNODES; n++) {
                    float2 a = *reinterpret_cast<const float2*>(Ik + n * istr + (pp << 1));
                    acc[n] = ffma2(a, w, acc[n]);
                }
            }
        }
        if (t + 1 < ntiles) {                     // commit prefetched tile
            float2* dstb = WTb + ((t + 1) & 1) * 4096;
#pragma unroll
            for (int i = 0; i < 16; i++) {
                int idx = tid + (i << 8);
                if (idx < cntN) dstb[idx] = r[i];
            }
        }
        __syncthreads();
    }

    if (tid < O) {
        float bj = g_arena[boff + tid];
#pragma unroll
        for (int n = 0; n < NNODES; n++) {
            float v = acc[n].x + acc[n].y + bj;
            if (act) v = (v >= 0.f) ? v : 0.2f * v;
            Out[n * RS + tid] = v;
        }
    }
    __syncthreads();
}

// ---------------------------------------------------------------------------
// main fused kernel: one CTA per batch
// ---------------------------------------------------------------------------
__global__ __launch_bounds__(NT) void gat_main(const float* __restrict__ x,
                                               float* __restrict__ out) {
    extern __shared__ float sm[];
    float* P0   = sm;
    float* P1   = P0 + NNODES * RS;
    float* P2   = P1 + NNODES * RS;
    float* P3   = P2 + NNODES * RS;
    float* WT   = P3 + NNODES * RS;   // 16384 floats
    float* XS   = WT + 16384;         // 184
    float* POOL = XS + 184;           // 256
    float* HD   = POOL + 256;         // 192

    const int tid = threadIdx.x;
    const int b   = blockIdx.x;

    // --- load x[b] (23x7) padded to 23x8 ---
    if (tid < 184) {
        int n = tid >> 3, k = tid & 7;
        XS[tid] = (k < 7) ? x[b * 161 + n * 7 + k] : 0.f;
    }
    __syncthreads();

    // --- message MLP ---
    gemm23(XS, 8,  P0, OFF_W1, OFF_B1, 8,   128, true,  WT, tid);  // H1
    gemm23(P0, RS, P1, OFF_W2, OFF_B2, 128, 256, true,  WT, tid);  // H2
    gemm23(P1, RS, P0, OFF_W3, OFF_B3, 256, 256, false, WT, tid);  // MSG

    // --- agg = colsum - msg ---
    {
        float s = 0.f;
#pragma unroll
        for (int n = 0; n < NNODES; n++) s += P0[n * RS + tid];
#pragma unroll
        for (int n = 0; n < NNODES; n++) P1[n * RS + tid] = s - P0[n * RS + tid];
    }
    __syncthreads();

    // --- QKV conv stacks + in_proj ---
    gemm23(P1, RS, P2, OFF_QW, OFF_QB, 256, 256, true,  WT, tid);  // Q
    gemm23(P2, RS, P0, OFF_WQ, OFF_BQ, 256, 256, false, WT, tid);  // qh (scaled)
    gemm23(P1, RS, P2, OFF_KW, OFF_KB, 256, 256, true,  WT, tid);  // K
    gemm23(P2, RS, P3, OFF_WK, OFF_BK, 256, 256, false, WT, tid);  // kh
    gemm23(P1, RS, P2, OFF_VW, OFF_VB, 256, 256, true,  WT, tid);  // V
    gemm23(P2, RS, P1, OFF_WV, OFF_BV, 256, 256, false, WT, tid);  // vh

    // --- kh -> khT[c][m] (stride 24) in WT scratch ---
    for (int idx = tid; idx < 5888; idx += NT) {
        int m = idx >> 8, c = idx & 255;
        WT[c * 24 + m] = P3[m * RS + c];
    }
    __syncthreads();

    // --- attention scores + softmax (warp per (h,n)); S -> P2[h][n][m] ---
    {
        int w = tid >> 5, lane = tid & 31;
        for (int task = w; task < 184; task += 8) {
            int h = task / 23, n = task - h * 23;
            const float* qrow = P0 + n * RS + h * 32;
            float accS = 0.f;
            if (lane < NNODES) {
#pragma unroll
                for (int d = 0; d < 32; d++)
                    accS += qrow[d] * WT[(h * 32 + d) * 24 + lane];
            }
            float v = (lane < NNODES) ? accS : -1e30f;
#pragma unroll
            for (int off = 16; off; off >>= 1)
                v = fmaxf(v, __shfl_xor_sync(0xffffffffu, v, off));
            float e = (lane < NNODES) ? __expf(accS - v) : 0.f;
            float ssum = e;
#pragma unroll
            for (int off = 16; off; off >>= 1)
                ssum += __shfl_xor_sync(0xffffffffu, ssum, off);
            if (lane < NNODES) P2[h * 529 + n * 23 + lane] = e / ssum;
        }
    }
    __syncthreads();

    // --- ctx = att @ vh -> P3 ---
    for (int idx = tid; idx < 5888; idx += NT) {
        int n = idx >> 8, c = idx & 255, h = c >> 5;
        const float* Sr = P2 + h * 529 + n * 23;
        const float* vc = P1 + c;
        float a = 0.f;
#pragma unroll
        for (int m = 0; m < NNODES; m++) a += Sr[m] * vc[m * RS];
        P3[n * RS + c] = a;
    }
    __syncthreads();

    // --- out_proj ---
    gemm23(P3, RS, P0, OFF_OW, OFF_OB, 256, 256, false, WT, tid);  // ctx proj

    // --- max pool over nodes ---
    {
        float mx = -1e30f;
#pragma unroll
        for (int n = 0; n < NNODES; n++) mx = fmaxf(mx, P0[n * RS + tid]);
        POOL[tid] = mx;
    }
    __syncthreads();

    // --- head: 256 -> 128 -> 64 -> 2 (weights LDG direct, L2-resident) ---
    if (tid < 128) {
        const float2* Wg = reinterpret_cast<const float2*>(g_arena + OFF_O1);
        float2 acc = make_float2(0.f, 0.f);
#pragma unroll 8
        for (int kp = 0; kp < 128; kp++) {
            float2 a = *reinterpret_cast<const float2*>(POOL + 2 * kp);
            acc = ffma2(a, Wg[kp * 128 + tid], acc);
        }
        float v = acc.x + acc.y + g_arena[OFF_OB1 + tid];
        HD[tid] = (v >= 0.f) ? v : 0.2f * v;
    }
    __syncthreads();
    if (tid < 64) {
        const float2* Wg = reinterpret_cast<const float2*>(g_arena + OFF_O2);
        float2 acc = make_float2(0.f, 0.f);
#pragma unroll 8
        for (int kp = 0; kp < 64; kp++) {
            float2 a = *reinterpret_cast<const float2*>(HD + 2 * kp);
            acc = ffma2(a, Wg[kp * 64 + tid], acc);
        }
        float v = acc.x + acc.y + g_arena[OFF_OB2 + tid];
        HD[128 + tid] = (v >= 0.f) ? v : 0.2f * v;
    }
    __syncthreads();
    if (tid < 2) {
        const float2* Wg = reinterpret_cast<const float2*>(g_arena + OFF_O3);
        float2 acc = make_float2(0.f, 0.f);
#pragma unroll
        for (int kp = 0; kp < 32; kp++) {
            float2 a = *reinterpret_cast<const float2*>(HD + 128 + 2 * kp);
            acc = ffma2(a, Wg[kp * 2 + tid], acc);
        }
        out[b * 2 + tid] = acc.x + acc.y + g_arena[OFF_OB3 + tid];
    }
}

// ---------------------------------------------------------------------------
extern "C" void kernel_launch(void* const* d_in, const int* in_sizes, int n_in,
                              void* d_out, int out_size) {
    const float* x     = (const float*)d_in[0];
    const float* mw1   = (const float*)d_in[1];
    const float* mb1   = (const float*)d_in[2];
    const float* mw2   = (const float*)d_in[3];
    const float* mb2   = (const float*)d_in[4];
    const float* mw3   = (const float*)d_in[5];
    const float* mb3   = (const float*)d_in[6];
    const float* qw    = (const float*)d_in[7];
    const float* qb    = (const float*)d_in[8];
    const float* kw    = (const float*)d_in[9];
    const float* kb    = (const float*)d_in[10];
    const float* vw    = (const float*)d_in[11];
    const float* vb    = (const float*)d_in[12];
    const float* inw   = (const float*)d_in[13];
    const float* inb   = (const float*)d_in[14];
    const float* outw  = (const float*)d_in[15];
    const float* outb  = (const float*)d_in[16];
    const float* ow1   = (const float*)d_in[17];
    const float* ob1   = (const float*)d_in[18];
    const float* ow2   = (const float*)d_in[19];
    const float* ob2   = (const float*)d_in[20];
    const float* ow3   = (const float*)d_in[21];
    const float* ob3   = (const float*)d_in[22];
    float* out = (float*)d_out;

    const float s = 0.17677669529663687f;  // 1/sqrt(32)

    // pack weights (transposed, k-pair interleaved) into arena
    pack_weights<<<32, NT>>>(mw1, 7,   128, 8,   1.f, OFF_W1);
    pack_weights<<<64, NT>>>(mw2, 128, 256, 128, 1.f, OFF_W2);
    pack_weights<<<64, NT>>>(mw3, 256, 256, 256, 1.f, OFF_W3);
    pack_weights<<<64, NT>>>(qw,  256, 256, 256, 1.f, OFF_QW);
    pack_weights<<<64, NT>>>(kw,  256, 256, 256, 1.f, OFF_KW);
    pack_weights<<<64, NT>>>(vw,  256, 256, 256, 1.f, OFF_VW);
    pack_weights<<<64, NT>>>(inw,             256, 256, 256, s,   OFF_WQ);
    pack_weights<<<64, NT>>>(inw + 256 * 256, 256, 256, 256, 1.f, OFF_WK);
    pack_weights<<<64, NT>>>(inw + 512 * 256, 256, 256, 256, 1.f, OFF_WV);
    pack_weights<<<64, NT>>>(outw, 256, 256, 256, 1.f, OFF_OW);
    pack_weights<<<64, NT>>>(ow1, 256, 128, 256, 1.f, OFF_O1);
    pack_weights<<<32, NT>>>(ow2, 128, 64,  128, 1.f, OFF_O2);
    pack_weights<<<1,  NT>>>(ow3, 64,  2,   64,  1.f, OFF_O3);
    pack_biases<<<1, NT>>>(mb1, mb2, mb3, qb, kb, vb, inb, outb, ob1, ob2, ob3);

    cudaFuncSetAttribute(gat_main, cudaFuncAttributeMaxDynamicSharedMemorySize,
                         SMEM_BYTES);
    int B = in_sizes[0] / 161;  // 23*7
    gat_main<<<B, NT, SMEM_BYTES>>>(x, out);
}

// round 2
// speedup vs baseline: 1.2114x; 1.2114x over previous
#include <cuda_runtime.h>
#include <cuda_bf16.h>

// ---------------------------------------------------------------------------
// gameGAT fused kernel v2: fp32 packed f32x2 FMA, 2-D register blocking
// (3 rows x 4 cols per thread), cp.async triple-buffered weight tiles.
// One CTA per batch element (16384 CTAs, 512 threads).
// ---------------------------------------------------------------------------

#define RS 260            // activation row stride in floats
#define NT 512            // threads per block (main kernel)
#define NNODES 23

// ---- arena layout (float offsets) ----
#define OFF_W1   0
#define OFF_W2   1024
#define OFF_W3   33792
#define OFF_QW   99328
#define OFF_KW   164864
#define OFF_VW   230400
#define OFF_WQ   295936
#define OFF_WK   361472
#define OFF_WV   427008
#define OFF_OW   492544
#define OFF_O1   558080
#define OFF_O2   590848
#define OFF_O3   599040
#define OFF_B1   599168
#define OFF_B2   599296
#define OFF_B3   599552
#define OFF_QB   599808
#define OFF_KB   600064
#define OFF_VB   600320
#define OFF_BQ   600576
#define OFF_BK   600832
#define OFF_BV   601088
#define OFF_OB   601344
#define OFF_OB1  601600
#define OFF_OB2  601728
#define OFF_OB3  601792
#define ARENA_SZ 601856

__device__ __align__(16) float g_arena[ARENA_SZ];

// smem plan (floats):
// P0..P3 : 4 * 23*260 = 23920
// WT     : 3 * 16*256 float2 = 24576 floats (weight tile triple buffer / khT)
// XS     : 184
// POOL   : 256
// HD     : 192
#define SMEM_FLOATS (23920 + 24576 + 184 + 256 + 192)
#define SMEM_BYTES  (SMEM_FLOATS * 4)

__device__ __forceinline__ float2 ffma2(float2 a, float2 b, float2 c) {
    unsigned long long ua = reinterpret_cast<unsigned long long&>(a);
    unsigned long long ub = reinterpret_cast<unsigned long long&>(b);
    unsigned long long uc = reinterpret_cast<unsigned long long&>(c);
    unsigned long long ud;
    asm("fma.rn.f32x2 %0, %1, %2, %3;" : "=l"(ud) : "l"(ua), "l"(ub), "l"(uc));
    return reinterpret_cast<float2&>(ud);
}

__device__ __forceinline__ unsigned smem_u32(const void* p) {
    return (unsigned)__cvta_generic_to_shared(p);
}
__device__ __forceinline__ void cp16(unsigned dst, const void* src) {
    asm volatile("cp.async.cg.shared.global [%0], [%1], 16;" :: "r"(dst), "l"(src));
}

// ---------------------------------------------------------------------------
// prep: pack weight [O][K] row-major -> arena [K/2][O] float2 (k-pair major)
// ---------------------------------------------------------------------------
__global__ void pack_weights(const float* __restrict__ src, int K, int O,
                             int Kpad, float scale, int dstOff) {
    int sz = (Kpad >> 1) * O * 2;
    for (int e = blockIdx.x * blockDim.x + threadIdx.x; e < sz;
         e += gridDim.x * blockDim.x) {
        int kp = e / (2 * O);
        int r  = e - kp * 2 * O;
        int j  = r >> 1;
        int t  = r & 1;
        int k  = 2 * kp + t;
        g_arena[dstOff + e] = (k < K) ? src[j * K + k] * scale : 0.f;
    }
}

__global__ void pack_biases(const float* b1, const float* b2, const float* b3,
                            const float* qb, const float* kb, const float* vb,
                            const float* inb, const float* ob,
                            const float* ob1, const float* ob2, const float* ob3) {
    const float s = 0.17677669529663687f;  // 1/sqrt(32)
    int t = threadIdx.x;
    for (int i = t; i < 128; i += 256) g_arena[OFF_B1 + i] = b1[i];
    for (int i = t; i < 256; i += 256) g_arena[OFF_B2 + i] = b2[i];
    for (int i = t; i < 256; i += 256) g_arena[OFF_B3 + i] = b3[i];
    for (int i = t; i < 256; i += 256) g_arena[OFF_QB + i] = qb[i];
    for (int i = t; i < 256; i += 256) g_arena[OFF_KB + i] = kb[i];
    for (int i = t; i < 256; i += 256) g_arena[OFF_VB + i] = vb[i];
    for (int i = t; i < 256; i += 256) g_arena[OFF_BQ + i] = inb[i] * s;
    for (int i = t; i < 256; i += 256) g_arena[OFF_BK + i] = inb[256 + i];
    for (int i = t; i < 256; i += 256) g_arena[OFF_BV + i] = inb[512 + i];
    for (int i = t; i < 256; i += 256) g_arena[OFF_OB + i] = ob[i];
    for (int i = t; i < 128; i += 256) g_arena[OFF_OB1 + i] = ob1[i];
    for (int i = t; i < 64;  i += 256) g_arena[OFF_OB2 + i] = ob2[i];
    for (int i = t; i < 2;   i += 256) g_arena[OFF_OB3 + i] = ob3[i];
}

// ---------------------------------------------------------------------------
// 23-row GEMM, 2-D register blocked. Thread owns R rows x 4 cols.
// Weights arena-packed [K/2][O] float2; tiles of 16 k-pairs streamed via
// cp.async into a triple-buffered smem ring (1 barrier per tile).
// ---------------------------------------------------------------------------
template<int O>
__device__ __noinline__ void gemmT(const float* __restrict__ In, int istr,
                                   float* __restrict__ Out,
                                   int woff, int boff, int K, bool act,
                                   float* __restrict__ WTf, int tid) {
    constexpr int CG = O / 4;              // colgroups
    constexpr int RG = NT / CG;            // rowgroups
    constexpr int R  = (23 + RG - 1) / RG; // rows per thread
    constexpr int TILE_F2 = 16 * O;        // float2 per tile buffer

    const int cg = tid & (CG - 1);
    const int rg = tid / CG;
    const int j0 = cg << 2;
    const int r0 = rg * R;

    const int npairs = K >> 1;
    const int ntiles = (npairs + 15) >> 4;
    const float2* WT2 = reinterpret_cast<const float2*>(WTf);
    const char* wsrc = reinterpret_cast<const char*>(g_arena + woff);
    const unsigned wdst = smem_u32(WTf);

    float2 acc[R][4];
#pragma unroll
    for (int r = 0; r < R; r++)
#pragma unroll
        for (int c = 0; c < 4; c++) acc[r][c] = make_float2(0.f, 0.f);

    auto stage = [&](int t) {
        int p0 = t << 4;
        int cnt = min(16, npairs - p0) * (O >> 1);   // 16B chunks
        const char* s = wsrc + (size_t)p0 * O * 8;
        unsigned d = wdst + (unsigned)(t % 3) * (TILE_F2 * 8);
        for (int c = tid; c < cnt; c += NT)
            cp16(d + c * 16, s + c * 16);
        asm volatile("cp.async.commit_group;");
    };

    stage(0);
    if (ntiles > 1) stage(1);

    for (int t = 0; t < ntiles; t++) {
        if (t + 1 < ntiles) asm volatile("cp.async.wait_group 1;");
        else                asm volatile("cp.async.wait_group 0;");
        __syncthreads();
        if (t + 2 < ntiles) stage(t + 2);

        const int pt2 = min(16, npairs - (t << 4)) >> 1;  // 2-kpair steps
        const float2* Wt = WT2 + (t % 3) * TILE_F2;
        const float* Ib = In + (t << 5);
#pragma unroll 2
        for (int s = 0; s < pt2; s++) {
            const float4* wp0 = reinterpret_cast<const float4*>(Wt + (2 * s) * O + j0);
            const float4* wp1 = reinterpret_cast<const float4*>(Wt + (2 * s + 1) * O + j0);
            float4 wA0 = wp0[0], wA1 = wp0[1];
            float4 wB0 = wp1[0], wB1 = wp1[1];
#pragma unroll
            for (int r = 0; r < R; r++) {
                float4 a = *reinterpret_cast<const float4*>(Ib + (r0 + r) * istr + 4 * s);
                float2 ax = make_float2(a.x, a.y);
                float2 az = make_float2(a.z, a.w);
                acc[r][0] = ffma2(ax, make_float2(wA0.x, wA0.y), acc[r][0]);
                acc[r][1] = ffma2(ax, make_float2(wA0.z, wA0.w), acc[r][1]);
                acc[r][2] = ffma2(ax, make_float2(wA1.x, wA1.y), acc[r][2]);
                acc[r][3] = ffma2(ax, make_float2(wA1.z, wA1.w), acc[r][3]);
                acc[r][0] = ffma2(az, make_float2(wB0.x, wB0.y), acc[r][0]);
                acc[r][1] = ffma2(az, make_float2(wB0.z, wB0.w), acc[r][1]);
                acc[r][2] = ffma2(az, make_float2(wB1.x, wB1.y), acc[r][2]);
                acc[r][3] = ffma2(az, make_float2(wB1.z, wB1.w), acc[r][3]);
            }
        }
    }

    const float4 bias = *reinterpret_cast<const float4*>(g_arena + boff + j0);
#pragma unroll
    for (int r = 0; r < R; r++) {
        int row = r0 + r;
        if (row < NNODES) {
            float4 o;
            o.x = acc[r][0].x + acc[r][0].y + bias.x;
            o.y = acc[r][1].x + acc[r][1].y + bias.y;
            o.z = acc[r][2].x + acc[r][2].y + bias.z;
            o.w = acc[r][3].x + acc[r][3].y + bias.w;
            if (act) {
                o.x = o.x >= 0.f ? o.x : 0.2f * o.x;
                o.y = o.y >= 0.f ? o.y : 0.2f * o.y;
                o.z = o.z >= 0.f ? o.z : 0.2f * o.z;
                o.w = o.w >= 0.f ? o.w : 0.2f * o.w;
            }
            *reinterpret_cast<float4*>(Out + row * RS + j0) = o;
        }
    }
    __syncthreads();
}

// ---------------------------------------------------------------------------
// main fused kernel: one CTA per batch
// ---------------------------------------------------------------------------
__global__ __launch_bounds__(NT) void gat_main(const float* __restrict__ x,
                                               float* __restrict__ out) {
    extern __shared__ float sm[];
    float* P0   = sm;
    float* P1   = P0 + NNODES * RS;
    float* P2   = P1 + NNODES * RS;
    float* P3   = P2 + NNODES * RS;
    float* WT   = P3 + NNODES * RS;   // 24576 floats
    float* XS   = WT + 24576;         // 184
    float* POOL = XS + 184;           // 256
    float* HD   = POOL + 256;         // 192

    const int tid = threadIdx.x;
    const int b   = blockIdx.x;

    // --- load x[b] (23x7) padded to 23x8 ---
    if (tid < 184) {
        int n = tid >> 3, k = tid & 7;
        XS[tid] = (k < 7) ? x[b * 161 + n * 7 + k] : 0.f;
    }
    __syncthreads();

    // --- message MLP ---
    gemmT<128>(XS, 8,  P0, OFF_W1, OFF_B1, 8,   true,  WT, tid);  // H1
    gemmT<256>(P0, RS, P1, OFF_W2, OFF_B2, 128, true,  WT, tid);  // H2
    gemmT<256>(P1, RS, P0, OFF_W3, OFF_B3, 256, false, WT, tid);  // MSG

    // --- agg = colsum - msg ---
    if (tid < 256) {
        float s = 0.f;
#pragma unroll
        for (int n = 0; n < NNODES; n++) s += P0[n * RS + tid];
#pragma unroll
        for (int n = 0; n < NNODES; n++) P1[n * RS + tid] = s - P0[n * RS + tid];
    }
    __syncthreads();

    // --- QKV conv stacks + in_proj ---
    gemmT<256>(P1, RS, P2, OFF_QW, OFF_QB, 256, true,  WT, tid);  // Q
    gemmT<256>(P2, RS, P0, OFF_WQ, OFF_BQ, 256, false, WT, tid);  // qh (scaled)
    gemmT<256>(P1, RS, P2, OFF_KW, OFF_KB, 256, true,  WT, tid);  // K
    gemmT<256>(P2, RS, P3, OFF_WK, OFF_BK, 256, false, WT, tid);  // kh
    gemmT<256>(P1, RS, P2, OFF_VW, OFF_VB, 256, true,  WT, tid);  // V
    gemmT<256>(P2, RS, P1, OFF_WV, OFF_BV, 256, false, WT, tid);  // vh

    // --- kh -> khT[c][m] (stride 24) in WT scratch ---
    for (int idx = tid; idx < 5888; idx += NT) {
        int m = idx >> 8, c = idx & 255;
        WT[c * 24 + m] = P3[m * RS + c];
    }
    __syncthreads();

    // --- attention scores + softmax (warp per (h,n)); S -> P2[h][n][m] ---
    {
        int w = tid >> 5, lane = tid & 31;
        for (int task = w; task < 184; task += NT / 32) {
            int h = task / 23, n = task - h * 23;
            const float* qrow = P0 + n * RS + h * 32;
            float accS = 0.f;
            if (lane < NNODES) {
#pragma unroll
                for (int d = 0; d < 32; d++)
                    accS += qrow[d] * WT[(h * 32 + d) * 24 + lane];
            }
            float v = (lane < NNODES) ? accS : -1e30f;
#pragma unroll
            for (int off = 16; off; off >>= 1)
                v = fmaxf(v, __shfl_xor_sync(0xffffffffu, v, off));
            float e = (lane < NNODES) ? __expf(accS - v) : 0.f;
            float ssum = e;
#pragma unroll
            for (int off = 16; off; off >>= 1)
                ssum += __shfl_xor_sync(0xffffffffu, ssum, off);
            if (lane < NNODES) P2[h * 529 + n * 23 + lane] = e / ssum;
        }
    }
    __syncthreads();

    // --- ctx = att @ vh -> P3 ---
    for (int idx = tid; idx < 5888; idx += NT) {
        int n = idx >> 8, c = idx & 255, h = c >> 5;
        const float* Sr = P2 + h * 529 + n * 23;
        const float* vc = P1 + c;
        float a = 0.f;
#pragma unroll
        for (int m = 0; m < NNODES; m++) a += Sr[m] * vc[m * RS];
        P3[n * RS + c] = a;
    }
    __syncthreads();

    // --- out_proj ---
    gemmT<256>(P3, RS, P0, OFF_OW, OFF_OB, 256, false, WT, tid);

    // --- max pool over nodes ---
    if (tid < 256) {
        float mx = -1e30f;
#pragma unroll
        for (int n = 0; n < NNODES; n++) mx = fmaxf(mx, P0[n * RS + tid]);
        POOL[tid] = mx;
    }
    __syncthreads();

    // --- head: 256 -> 128 -> 64 -> 2 (weights LDG direct, L2-resident) ---
    if (tid < 128) {
        const float2* Wg = reinterpret_cast<const float2*>(g_arena + OFF_O1);
        float2 acc = make_float2(0.f, 0.f);
#pragma unroll 8
        for (int kp = 0; kp < 128; kp++) {
            float2 a = *reinterpret_cast<const float2*>(POOL + 2 * kp);
            acc = ffma2(a, Wg[kp * 128 + tid], acc);
        }
        float v = acc.x + acc.y + g_arena[OFF_OB1 + tid];
        HD[tid] = (v >= 0.f) ? v : 0.2f * v;
    }
    __syncthreads();
    if (tid < 64) {
        const float2* Wg = reinterpret_cast<const float2*>(g_arena + OFF_O2);
        float2 acc = make_float2(0.f, 0.f);
#pragma unroll 8
        for (int kp = 0; kp < 64; kp++) {
            float2 a = *reinterpret_cast<const float2*>(HD + 2 * kp);
            acc = ffma2(a, Wg[kp * 64 + tid], acc);
        }
        float v = acc.x + acc.y + g_arena[OFF_OB2 + tid];
        HD[128 + tid] = (v >= 0.f) ? v : 0.2f * v;
    }
    __syncthreads();
    if (tid < 2) {
        const float2* Wg = reinterpret_cast<const float2*>(g_arena + OFF_O3);
        float2 acc = make_float2(0.f, 0.f);
#pragma unroll
        for (int kp = 0; kp < 32; kp++) {
            float2 a = *reinterpret_cast<const float2*>(HD + 128 + 2 * kp);
            acc = ffma2(a, Wg[kp * 2 + tid], acc);
        }
        out[b * 2 + tid] = acc.x + acc.y + g_arena[OFF_OB3 + tid];
    }
}

// ---------------------------------------------------------------------------
extern "C" void kernel_launch(void* const* d_in, const int* in_sizes, int n_in,
                              void* d_out, int out_size) {
    const float* x     = (const float*)d_in[0];
    const float* mw1   = (const float*)d_in[1];
    const float* mb1   = (const float*)d_in[2];
    const float* mw2   = (const float*)d_in[3];
    const float* mb2   = (const float*)d_in[4];
    const float* mw3   = (const float*)d_in[5];
    const float* mb3   = (const float*)d_in[6];
    const float* qw    = (const float*)d_in[7];
    const float* qb    = (const float*)d_in[8];
    const float* kw    = (const float*)d_in[9];
    const float* kb    = (const float*)d_in[10];
    const float* vw    = (const float*)d_in[11];
    const float* vb    = (const float*)d_in[12];
    const float* inw   = (const float*)d_in[13];
    const float* inb   = (const float*)d_in[14];
    const float* outw  = (const float*)d_in[15];
    const float* outb  = (const float*)d_in[16];
    const float* ow1   = (const float*)d_in[17];
    const float* ob1   = (const float*)d_in[18];
    const float* ow2   = (const float*)d_in[19];
    const float* ob2   = (const float*)d_in[20];
    const float* ow3   = (const float*)d_in[21];
    const float* ob3   = (const float*)d_in[22];
    float* out = (float*)d_out;

    const float s = 0.17677669529663687f;  // 1/sqrt(32)

    pack_weights<<<32, 256>>>(mw1, 7,   128, 8,   1.f, OFF_W1);
    pack_weights<<<64, 256>>>(mw2, 128, 256, 128, 1.f, OFF_W2);
    pack_weights<<<64, 256>>>(mw3, 256, 256, 256, 1.f, OFF_W3);
    pack_weights<<<64, 256>>>(qw,  256, 256, 256, 1.f, OFF_QW);
    pack_weights<<<64, 256>>>(kw,  256, 256, 256, 1.f, OFF_KW);
    pack_weights<<<64, 256>>>(vw,  256, 256, 256, 1.f, OFF_VW);
    pack_weights<<<64, 256>>>(inw,             256, 256, 256, s,   OFF_WQ);
    pack_weights<<<64, 256>>>(inw + 256 * 256, 256, 256, 256, 1.f, OFF_WK);
    pack_weights<<<64, 256>>>(inw + 512 * 256, 256, 256, 256, 1.f, OFF_WV);
    pack_weights<<<64, 256>>>(outw, 256, 256, 256, 1.f, OFF_OW);
    pack_weights<<<64, 256>>>(ow1, 256, 128, 256, 1.f, OFF_O1);
    pack_weights<<<32, 256>>>(ow2, 128, 64,  128, 1.f, OFF_O2);
    pack_weights<<<1,  256>>>(ow3, 64,  2,   64,  1.f, OFF_O3);
    pack_biases<<<1, 256>>>(mb1, mb2, mb3, qb, kb, vb, inb, outb, ob1, ob2, ob3);

    cudaFuncSetAttribute(gat_main, cudaFuncAttributeMaxDynamicSharedMemorySize,
                         SMEM_BYTES);
    int B = in_sizes[0] / 161;  // 23*7
    gat_main<<<B, NT, SMEM_BYTES>>>(x, out);
}

// round 3
// speedup vs baseline: 1.2117x; 1.0003x over previous
#include <cuda_runtime.h>
#include <cuda_bf16.h>

// ---------------------------------------------------------------------------
// gameGAT fused kernel v2: fp32 packed f32x2 FMA, 2-D register blocking
// (3 rows x 4 cols per thread), cp.async triple-buffered weight tiles.
// One CTA per batch element (16384 CTAs, 512 threads).
// ---------------------------------------------------------------------------

#define RS 260            // activation row stride in floats
#define NT 512            // threads per block (main kernel)
#define NNODES 23

// ---- arena layout (float offsets) ----
#define OFF_W1   0
#define OFF_W2   1024
#define OFF_W3   33792
#define OFF_QW   99328
#define OFF_KW   164864
#define OFF_VW   230400
#define OFF_WQ   295936
#define OFF_WK   361472
#define OFF_WV   427008
#define OFF_OW   492544
#define OFF_O1   558080
#define OFF_O2   590848
#define OFF_O3   599040
#define OFF_B1   599168
#define OFF_B2   599296
#define OFF_B3   599552
#define OFF_QB   599808
#define OFF_KB   600064
#define OFF_VB   600320
#define OFF_BQ   600576
#define OFF_BK   600832
#define OFF_BV   601088
#define OFF_OB   601344
#define OFF_OB1  601600
#define OFF_OB2  601728
#define OFF_OB3  601792
#define ARENA_SZ 601856

__device__ __align__(16) float g_arena[ARENA_SZ];

// smem plan (floats):
// P0..P3 : 4 * 23*260 = 23920
// WT     : 3 * 16*256 float2 = 24576 floats (weight tile triple buffer / khT)
// XS     : 184
// POOL   : 256
// HD     : 192
#define SMEM_FLOATS (23920 + 24576 + 184 + 256 + 192)
#define SMEM_BYTES  (SMEM_FLOATS * 4)

__device__ __forceinline__ float2 ffma2(float2 a, float2 b, float2 c) {
    unsigned long long ua = reinterpret_cast<unsigned long long&>(a);
    unsigned long long ub = reinterpret_cast<unsigned long long&>(b);
    unsigned long long uc = reinterpret_cast<unsigned long long&>(c);
    unsigned long long ud;
    asm("fma.rn.f32x2 %0, %1, %2, %3;" : "=l"(ud) : "l"(ua), "l"(ub), "l"(uc));
    return reinterpret_cast<float2&>(ud);
}

__device__ __forceinline__ unsigned smem_u32(const void* p) {
    return (unsigned)__cvta_generic_to_shared(p);
}
__device__ __forceinline__ void cp16(unsigned dst, const void* src) {
    asm volatile("cp.async.cg.shared.global [%0], [%1], 16;" :: "r"(dst), "l"(src));
}

// ---------------------------------------------------------------------------
// prep: pack weight [O][K] row-major -> arena [K/2][O] float2 (k-pair major)
// ---------------------------------------------------------------------------
__global__ void pack_weights(const float* __restrict__ src, int K, int O,
                             int Kpad, float scale, int dstOff) {
    int sz = (Kpad >> 1) * O * 2;
    for (int e = blockIdx.x * blockDim.x + threadIdx.x; e < sz;
         e += gridDim.x * blockDim.x) {
        int kp = e / (2 * O);
        int r  = e - kp * 2 * O;
        int j  = r >> 1;
        int t  = r & 1;
        int k  = 2 * kp + t;
        g_arena[dstOff + e] = (k < K) ? src[j * K + k] * scale : 0.f;
    }
}

__global__ void pack_biases(const float* b1, const float* b2, const float* b3,
                            const float* qb, const float* kb, const float* vb,
                            const float* inb, const float* ob,
                            const float* ob1, const float* ob2, const float* ob3) {
    const float s = 0.17677669529663687f;  // 1/sqrt(32)
    int t = threadIdx.x;
    for (int i = t; i < 128; i += 256) g_arena[OFF_B1 + i] = b1[i];
    for (int i = t; i < 256; i += 256) g_arena[OFF_B2 + i] = b2[i];
    for (int i = t; i < 256; i += 256) g_arena[OFF_B3 + i] = b3[i];
    for (int i = t; i < 256; i += 256) g_arena[OFF_QB + i] = qb[i];
    for (int i = t; i < 256; i += 256) g_arena[OFF_KB + i] = kb[i];
    for (int i = t; i < 256; i += 256) g_arena[OFF_VB + i] = vb[i];
    for (int i = t; i < 256; i += 256) g_arena[OFF_BQ + i] = inb[i] * s;
    for (int i = t; i < 256; i += 256) g_arena[OFF_BK + i] = inb[256 + i];
    for (int i = t; i < 256; i += 256) g_arena[OFF_BV + i] = inb[512 + i];
    for (int i = t; i < 256; i += 256) g_arena[OFF_OB + i] = ob[i];
    for (int i = t; i < 128; i += 256) g_arena[OFF_OB1 + i] = ob1[i];
    for (int i = t; i < 64;  i += 256) g_arena[OFF_OB2 + i] = ob2[i];
    for (int i = t; i < 2;   i += 256) g_arena[OFF_OB3 + i] = ob3[i];
}

// ---------------------------------------------------------------------------
// 23-row GEMM, 2-D register blocked. Thread owns R rows x 4 cols.
// Weights arena-packed [K/2][O] float2; tiles of 16 k-pairs streamed via
// cp.async into a triple-buffered smem ring (1 barrier per tile).
// ---------------------------------------------------------------------------
template<int O>
__device__ __noinline__ void gemmT(const float* __restrict__ In, int istr,
                                   float* __restrict__ Out,
                                   int woff, int boff, int K, bool act,
                                   float* __restrict__ WTf, int tid) {
    constexpr int CG = O / 4;              // colgroups
    constexpr int RG = NT / CG;            // rowgroups
    constexpr int R  = (23 + RG - 1) / RG; // rows per thread
    constexpr int TILE_F2 = 16 * O;        // float2 per tile buffer

    const int cg = tid & (CG - 1);
    const int rg = tid / CG;
    const int j0 = cg << 2;
    const int r0 = rg * R;

    const int npairs = K >> 1;
    const int ntiles = (npairs + 15) >> 4;
    const float2* WT2 = reinterpret_cast<const float2*>(WTf);
    const char* wsrc = reinterpret_cast<const char*>(g_arena + woff);
    const unsigned wdst = smem_u32(WTf);

    float2 acc[R][4];
#pragma unroll
    for (int r = 0; r < R; r++)
#pragma unroll
        for (int c = 0; c < 4; c++) acc[r][c] = make_float2(0.f, 0.f);

    auto stage = [&](int t) {
        int p0 = t << 4;
        int cnt = min(16, npairs - p0) * (O >> 1);   // 16B chunks
        const char* s = wsrc + (size_t)p0 * O * 8;
        unsigned d = wdst + (unsigned)(t % 3) * (TILE_F2 * 8);
        for (int c = tid; c < cnt; c += NT)
            cp16(d + c * 16, s + c * 16);
        asm volatile("cp.async.commit_group;");
    };

    stage(0);
    if (ntiles > 1) stage(1);

    for (int t = 0; t < ntiles; t++) {
        if (t + 1 < ntiles) asm volatile("cp.async.wait_group 1;");
        else                asm volatile("cp.async.wait_group 0;");
        __syncthreads();
        if (t + 2 < ntiles) stage(t + 2);

        const int pt2 = min(16, npairs - (t << 4)) >> 1;  // 2-kpair steps
        const float2* Wt = WT2 + (t % 3) * TILE_F2;
        const float* Ib = In + (t << 5);
#pragma unroll 2
        for (int s = 0; s < pt2; s++) {
            const float4* wp0 = reinterpret_cast<const float4*>(Wt + (2 * s) * O + j0);
            const float4* wp1 = reinterpret_cast<const float4*>(Wt + (2 * s + 1) * O + j0);
            float4 wA0 = wp0[0], wA1 = wp0[1];
            float4 wB0 = wp1[0], wB1 = wp1[1];
#pragma unroll
            for (int r = 0; r < R; r++) {
                float4 a = *reinterpret_cast<const float4*>(Ib + (r0 + r) * istr + 4 * s);
                float2 ax = make_float2(a.x, a.y);
                float2 az = make_float2(a.z, a.w);
                acc[r][0] = ffma2(ax, make_float2(wA0.x, wA0.y), acc[r][0]);
                acc[r][1] = ffma2(ax, make_float2(wA0.z, wA0.w), acc[r][1]);
                acc[r][2] = ffma2(ax, make_float2(wA1.x, wA1.y), acc[r][2]);
                acc[r][3] = ffma2(ax, make_float2(wA1.z, wA1.w), acc[r][3]);
                acc[r][0] = ffma2(az, make_float2(wB0.x, wB0.y), acc[r][0]);
                acc[r][1] = ffma2(az, make_float2(wB0.z, wB0.w), acc[r][1]);
                acc[r][2] = ffma2(az, make_float2(wB1.x, wB1.y), acc[r][2]);
                acc[r][3] = ffma2(az, make_float2(wB1.z, wB1.w), acc[r][3]);
            }
        }
    }

    const float4 bias = *reinterpret_cast<const float4*>(g_arena + boff + j0);
#pragma unroll
    for (int r = 0; r < R; r++) {
        int row = r0 + r;
        if (row < NNODES) {
            float4 o;
            o.x = acc[r][0].x + acc[r][0].y + bias.x;
            o.y = acc[r][1].x + acc[r][1].y + bias.y;
            o.z = acc[r][2].x + acc[r][2].y + bias.z;
            o.w = acc[r][3].x + acc[r][3].y + bias.w;
            if (act) {
                o.x = o.x >= 0.f ? o.x : 0.2f * o.x;
                o.y = o.y >= 0.f ? o.y : 0.2f * o.y;
                o.z = o.z >= 0.f ? o.z : 0.2f * o.z;
                o.w = o.w >= 0.f ? o.w : 0.2f * o.w;
            }
            *reinterpret_cast<float4*>(Out + row * RS + j0) = o;
        }
    }
    __syncthreads();
}

// ---------------------------------------------------------------------------
// main fused kernel: one CTA per batch
// ---------------------------------------------------------------------------
__global__ __launch_bounds__(NT) void gat_main(const float* __restrict__ x,
                                               float* __restrict__ out) {
    extern __shared__ float sm[];
    float* P0   = sm;
    float* P1   = P0 + NNODES * RS;
    float* P2   = P1 + NNODES * RS;
    float* P3   = P2 + NNODES * RS;
    float* WT   = P3 + NNODES * RS;   // 24576 floats
    float* XS   = WT + 24576;         // 184
    float* POOL = XS + 184;           // 256
    float* HD   = POOL + 256;         // 192

    const int tid = threadIdx.x;
    const int b   = blockIdx.x;

    // --- load x[b] (23x7) padded to 23x8 ---
    if (tid < 184) {
        int n = tid >> 3, k = tid & 7;
        XS[tid] = (k < 7) ? x[b * 161 + n * 7 + k] : 0.f;
    }
    __syncthreads();

    // --- message MLP ---
    gemmT<128>(XS, 8,  P0, OFF_W1, OFF_B1, 8,   true,  WT, tid);  // H1
    gemmT<256>(P0, RS, P1, OFF_W2, OFF_B2, 128, true,  WT, tid);  // H2
    gemmT<256>(P1, RS, P0, OFF_W3, OFF_B3, 256, false, WT, tid);  // MSG

    // --- agg = colsum - msg ---
    if (tid < 256) {
        float s = 0.f;
#pragma unroll
        for (int n = 0; n < NNODES; n++) s += P0[n * RS + tid];
#pragma unroll
        for (int n = 0; n < NNODES; n++) P1[n * RS + tid] = s - P0[n * RS + tid];
    }
    __syncthreads();

    // --- QKV conv stacks + in_proj ---
    gemmT<256>(P1, RS, P2, OFF_QW, OFF_QB, 256, true,  WT, tid);  // Q
    gemmT<256>(P2, RS, P0, OFF_WQ, OFF_BQ, 256, false, WT, tid);  // qh (scaled)
    gemmT<256>(P1, RS, P2, OFF_KW, OFF_KB, 256, true,  WT, tid);  // K
    gemmT<256>(P2, RS, P3, OFF_WK, OFF_BK, 256, false, WT, tid);  // kh
    gemmT<256>(P1, RS, P2, OFF_VW, OFF_VB, 256, true,  WT, tid);  // V
    gemmT<256>(P2, RS, P1, OFF_WV, OFF_BV, 256, false, WT, tid);  // vh

    // --- kh -> khT[c][m] (stride 24) in WT scratch ---
    for (int idx = tid; idx < 5888; idx += NT) {
        int m = idx >> 8, c = idx & 255;
        WT[c * 24 + m] = P3[m * RS + c];
    }
    __syncthreads();

    // --- attention scores + softmax (warp per (h,n)); S -> P2[h][n][m] ---
    {
        int w = tid >> 5, lane = tid & 31;
        for (int task = w; task < 184; task += NT / 32) {
            int h = task / 23, n = task - h * 23;
            const float* qrow = P0 + n * RS + h * 32;
            float accS = 0.f;
            if (lane < NNODES) {
#pragma unroll
                for (int d = 0; d < 32; d++)
                    accS += qrow[d] * WT[(h * 32 + d) * 24 + lane];
            }
            float v = (lane < NNODES) ? accS : -1e30f;
#pragma unroll
            for (int off = 16; off; off >>= 1)
                v = fmaxf(v, __shfl_xor_sync(0xffffffffu, v, off));
            float e = (lane < NNODES) ? __expf(accS - v) : 0.f;
            float ssum = e;
#pragma unroll
            for (int off = 16; off; off >>= 1)
                ssum += __shfl_xor_sync(0xffffffffu, ssum, off);
            if (lane < NNODES) P2[h * 529 + n * 23 + lane] = e / ssum;
        }
    }
    __syncthreads();

    // --- ctx = att @ vh -> P3 ---
    for (int idx = tid; idx < 5888; idx += NT) {
        int n = idx >> 8, c = idx & 255, h = c >> 5;
        const float* Sr = P2 + h * 529 + n * 23;
        const float* vc = P1 + c;
        float a = 0.f;
#pragma unroll
        for (int m = 0; m < NNODES; m++) a += Sr[m] * vc[m * RS];
        P3[n * RS + c] = a;
    }
    __syncthreads();

    // --- out_proj ---
    gemmT<256>(P3, RS, P0, OFF_OW, OFF_OB, 256, false, WT, tid);

    // --- max pool over nodes ---
    if (tid < 256) {
        float mx = -1e30f;
#pragma unroll
        for (int n = 0; n < NNODES; n++) mx = fmaxf(mx, P0[n * RS + tid]);
        POOL[tid] = mx;
    }
    __syncthreads();

    // --- head: 256 -> 128 -> 64 -> 2 (weights LDG direct, L2-resident) ---
    if (tid < 128) {
        const float2* Wg = reinterpret_cast<const float2*>(g_arena + OFF_O1);
        float2 acc = make_float2(0.f, 0.f);
#pragma unroll 8
        for (int kp = 0; kp < 128; kp++) {
            float2 a = *reinterpret_cast<const float2*>(POOL + 2 * kp);
            acc = ffma2(a, Wg[kp * 128 + tid], acc);
        }
        float v = acc.x + acc.y + g_arena[OFF_OB1 + tid];
        HD[tid] = (v >= 0.f) ? v : 0.2f * v;
    }
    __syncthreads();
    if (tid < 64) {
        const float2* Wg = reinterpret_cast<const float2*>(g_arena + OFF_O2);
        float2 acc = make_float2(0.f, 0.f);
#pragma unroll 8
        for (int kp = 0; kp < 64; kp++) {
            float2 a = *reinterpret_cast<const float2*>(HD + 2 * kp);
            acc = ffma2(a, Wg[kp * 64 + tid], acc);
        }
        float v = acc.x + acc.y + g_arena[OFF_OB2 + tid];
        HD[128 + tid] = (v >= 0.f) ? v : 0.2f * v;
    }
    __syncthreads();
    if (tid < 2) {
        const float2* Wg = reinterpret_cast<const float2*>(g_arena + OFF_O3);
        float2 acc = make_float2(0.f, 0.f);
#pragma unroll
        for (int kp = 0; kp < 32; kp++) {
            float2 a = *reinterpret_cast<const float2*>(HD + 128 + 2 * kp);
            acc = ffma2(a, Wg[kp * 2 + tid], acc);
        }
        out[b * 2 + tid] = acc.x + acc.y + g_arena[OFF_OB3 + tid];
    }
}

// ---------------------------------------------------------------------------
extern "C" void kernel_launch(void* const* d_in, const int* in_sizes, int n_in,
                              void* d_out, int out_size) {
    const float* x     = (const float*)d_in[0];
    const float* mw1   = (const float*)d_in[1];
    const float* mb1   = (const float*)d_in[2];
    const float* mw2   = (const float*)d_in[3];
    const float* mb2   = (const float*)d_in[4];
    const float* mw3   = (const float*)d_in[5];
    const float* mb3   = (const float*)d_in[6];
    const float* qw    = (const float*)d_in[7];
    const float* qb    = (const float*)d_in[8];
    const float* kw    = (const float*)d_in[9];
    const float* kb    = (const float*)d_in[10];
    const float* vw    = (const float*)d_in[11];
    const float* vb    = (const float*)d_in[12];
    const float* inw   = (const float*)d_in[13];
    const float* inb   = (const float*)d_in[14];
    const float* outw  = (const float*)d_in[15];
    const float* outb  = (const float*)d_in[16];
    const float* ow1   = (const float*)d_in[17];
    const float* ob1   = (const float*)d_in[18];
    const float* ow2   = (const float*)d_in[19];
    const float* ob2   = (const float*)d_in[20];
    const float* ow3   = (const float*)d_in[21];
    const float* ob3   = (const float*)d_in[22];
    float* out = (float*)d_out;

    const float s = 0.17677669529663687f;  // 1/sqrt(32)

    pack_weights<<<32, 256>>>(mw1, 7,   128, 8,   1.f, OFF_W1);
    pack_weights<<<64, 256>>>(mw2, 128, 256, 128, 1.f, OFF_W2);
    pack_weights<<<64, 256>>>(mw3, 256, 256, 256, 1.f, OFF_W3);
    pack_weights<<<64, 256>>>(qw,  256, 256, 256, 1.f, OFF_QW);
    pack_weights<<<64, 256>>>(kw,  256, 256, 256, 1.f, OFF_KW);
    pack_weights<<<64, 256>>>(vw,  256, 256, 256, 1.f, OFF_VW);
    pack_weights<<<64, 256>>>(inw,             256, 256, 256, s,   OFF_WQ);
    pack_weights<<<64, 256>>>(inw + 256 * 256, 256, 256, 256, 1.f, OFF_WK);
    pack_weights<<<64, 256>>>(inw + 512 * 256, 256, 256, 256, 1.f, OFF_WV);
    pack_weights<<<64, 256>>>(outw, 256, 256, 256, 1.f, OFF_OW);
    pack_weights<<<64, 256>>>(ow1, 256, 128, 256, 1.f, OFF_O1);
    pack_weights<<<32, 256>>>(ow2, 128, 64,  128, 1.f, OFF_O2);
    pack_weights<<<1,  256>>>(ow3, 64,  2,   64,  1.f, OFF_O3);
    pack_biases<<<1, 256>>>(mb1, mb2, mb3, qb, kb, vb, inb, outb, ob1, ob2, ob3);

    cudaFuncSetAttribute(gat_main, cudaFuncAttributeMaxDynamicSharedMemorySize,
                         SMEM_BYTES);
    int B = in_sizes[0] / 161;  // 23*7
    gat_main<<<B, NT, SMEM_BYTES>>>(x, out);
}

// round 6
// speedup vs baseline: 5.1231x; 4.2279x over previous
#include <cuda_runtime.h>
#include <cuda_bf16.h>
#include <cstdint>

#define NN 23
#define BSZ 16384
#define MTOT (BSZ * NN)          // 376832 = 2944*128
#define NT 256
#define SWZ(o) ((o) ^ (((o) >> 3) & 0x70))

// ---------------- 4 big aliased regions + 1 small region -------------------
// REG = MTOT*256*4 bytes: holds either a bf16 hi/lo image pair or an f32 plane
#define REGB ((size_t)MTOT * 256 * 4)      // 385,875,968
__device__ __align__(128) char g_R0[REGB];
__device__ __align__(128) char g_R1[REGB];
__device__ __align__(128) char g_R2[REGB];
__device__ __align__(128) char g_R3[REGB];
// small: PLh | PLl | H1h | H1l | H2(f32)
#define RS_PLH 0
#define RS_PLL ((size_t)BSZ * 256 * 2)
#define RS_H1H ((size_t)BSZ * 256 * 4)
#define RS_H1L (RS_H1H + (size_t)BSZ * 128 * 2)
#define RS_H2  (RS_H1H + (size_t)BSZ * 128 * 4)
#define RS_SZ  (RS_H2 + (size_t)BSZ * 64 * 4)
__device__ __align__(128) char g_RS[RS_SZ];

// ---------------- weight arena (pre-swizzled chunk images), elem offsets
#define W1OFF 0
#define W2OFF 8192
#define W3OFF 40960
#define QWOFF 106496
#define KWOFF 172032
#define VWOFF 237568
#define WQOFF 303104
#define WKOFF 368640
#define WVOFF 434176
#define OWOFF 499712
#define O1OFF 565248
#define O2OFF 598016
#define WSZ   606208
__device__ __align__(16) __nv_bfloat16 g_Wh[WSZ];
__device__ __align__(16) __nv_bfloat16 g_Wl[WSZ];

// bias arena (f32) + head3 weights
#define B1O 0
#define B2O 128
#define B3O 384
#define QBO 640
#define KBO 896
#define VBO 1152
#define BQO 1408
#define BKO 1664
#define BVO 1920
#define OBO 2176
#define OB1O 2432
#define OB2O 2560
#define W3HO 2624
#define B3HO 2752
__device__ float g_Ba[2816];

// ---------------- helpers
__device__ __forceinline__ unsigned smem_u32(const void* p) {
    return (unsigned)__cvta_generic_to_shared(p);
}
__device__ __forceinline__ void cp16(unsigned d, const void* s) {
    asm volatile("cp.async.cg.shared.global [%0], [%1], 16;" :: "r"(d), "l"(s));
}
__device__ __forceinline__ void ldm4(uint32_t* r, unsigned a) {
    asm volatile("ldmatrix.sync.aligned.m8n8.x4.shared.b16 {%0,%1,%2,%3}, [%4];"
                 : "=r"(r[0]), "=r"(r[1]), "=r"(r[2]), "=r"(r[3]) : "r"(a));
}
__device__ __forceinline__ void mma16816(float* c, const uint32_t* a,
                                         const uint32_t* b) {
    asm volatile(
        "mma.sync.aligned.m16n8k16.row.col.f32.bf16.bf16.f32 "
        "{%0,%1,%2,%3},{%4,%5,%6,%7},{%8,%9},{%0,%1,%2,%3};"
        : "+f"(c[0]), "+f"(c[1]), "+f"(c[2]), "+f"(c[3])
        : "r"(a[0]), "r"(a[1]), "r"(a[2]), "r"(a[3]), "r"(b[0]), "r"(b[1]));
}
__device__ __forceinline__ void split2(float a, float b,
                                       __nv_bfloat162& h2, __nv_bfloat162& l2) {
    __nv_bfloat16 ah = __float2bfloat16(a), bh = __float2bfloat16(b);
    h2 = __halves2bfloat162(ah, bh);
    l2 = __halves2bfloat162(__float2bfloat16(a - __bfloat162float(ah)),
                            __float2bfloat16(b - __bfloat162float(bh)));
}

// ---------------- prep kernels
__global__ void prep_w(const float* __restrict__ src, int O, int K, int nch,
                       float scale, int off) {
    int tot = nch * O * 64;
    for (int e = blockIdx.x * blockDim.x + threadIdx.x; e < tot;
         e += gridDim.x * blockDim.x) {
        int kc = e / (O * 64), rem = e - kc * O * 64;
        int r = rem >> 6, kk = rem & 63, k = kc * 64 + kk;
        float v = (k < K) ? src[r * K + k] * scale : 0.f;
        __nv_bfloat16 h = __float2bfloat16(v);
        int dst = off + kc * O * 64 + (SWZ(r * 128 + kk * 2) >> 1);
        g_Wh[dst] = h;
        g_Wl[dst] = __float2bfloat16(v - __bfloat162float(h));
    }
}
__global__ void prep_x(const float* __restrict__ x,
                       __nv_bfloat16* __restrict__ XAh,
                       __nv_bfloat16* __restrict__ XAl) {
    for (size_t e = (size_t)blockIdx.x * blockDim.x + threadIdx.x;
         e < (size_t)MTOT * 64; e += (size_t)gridDim.x * blockDim.x) {
        size_t m = e >> 6;
        int c = (int)(e & 63);
        float v = (c < 7) ? x[m * 7 + c] : 0.f;
        size_t tile = m >> 7;
        int rt = (int)(m & 127);
        size_t dst = tile * 8192 + (SWZ(rt * 128 + c * 2) >> 1);
        __nv_bfloat16 h = __float2bfloat16(v);
        XAh[dst] = h;
        XAl[dst] = __float2bfloat16(v - __bfloat162float(h));
    }
}
__global__ void prep_bias(const float* b1, const float* b2, const float* b3,
                          const float* qb, const float* kb, const float* vb,
                          const float* inb, const float* ob, const float* ob1,
                          const float* ob2, const float* ow3, const float* ob3) {
    const float s = 0.17677669529663687f;
    int t = threadIdx.x;
    for (int i = t; i < 128; i += 256) g_Ba[B1O + i] = b1[i];
    for (int i = t; i < 256; i += 256) g_Ba[B2O + i] = b2[i];
    for (int i = t; i < 256; i += 256) g_Ba[B3O + i] = b3[i];
    for (int i = t; i < 256; i += 256) g_Ba[QBO + i] = qb[i];
    for (int i = t; i < 256; i += 256) g_Ba[KBO + i] = kb[i];
    for (int i = t; i < 256; i += 256) g_Ba[VBO + i] = vb[i];
    for (int i = t; i < 256; i += 256) g_Ba[BQO + i] = inb[i] * s;
    for (int i = t; i < 256; i += 256) g_Ba[BKO + i] = inb[256 + i];
    for (int i = t; i < 256; i += 256) g_Ba[BVO + i] = inb[512 + i];
    for (int i = t; i < 256; i += 256) g_Ba[OBO + i] = ob[i];
    for (int i = t; i < 128; i += 256) g_Ba[OB1O + i] = ob1[i];
    for (int i = t; i < 64;  i += 256) g_Ba[OB2O + i] = ob2[i];
    for (int i = t; i < 128; i += 256) g_Ba[W3HO + i] = ow3[i];
    for (int i = t; i < 2;   i += 256) g_Ba[B3HO + i] = ob3[i];
}

// ---------------------------------------------------------------------------
// HMMA GEMM: CTA tile M=128 x NB (<=128), K = nch*64, 3-term bf16 split.
// 8 warps, warp tile 32 x NB/2. Double-buffered cp.async chunks.
// ---------------------------------------------------------------------------
template<int NB>
__global__ void __launch_bounds__(NT, 1) gemm_hmma(
    const __nv_bfloat16* __restrict__ Ah_, const __nv_bfloat16* __restrict__ Al_,
    int nch, int woff, int Nfull, int boff, int act, int outmode,
    __nv_bfloat16* __restrict__ Oh, __nv_bfloat16* __restrict__ Ol,
    float* __restrict__ Of) {
    extern __shared__ char smem[];
    const unsigned sb = smem_u32(smem) + 1024;
    constexpr int NJ = NB / 16;
    constexpr int BUF = 32768 + NB * 256;
    const int tid = threadIdx.x, w = tid >> 5, l = tid & 31;
    const int m0 = (w >> 1) * 32, n0l = (w & 1) * (NB / 2);
    const int n0g = blockIdx.y * NB;

    float acc[2][NJ][4];
#pragma unroll
    for (int mi = 0; mi < 2; mi++)
#pragma unroll
        for (int nj = 0; nj < NJ; nj++)
#pragma unroll
            for (int q = 0; q < 4; q++) acc[mi][nj][q] = 0.f;

    auto stage = [&](int c) {
        size_t ao = ((size_t)blockIdx.x * nch + c) * 16384;
        const char* pAh = (const char*)Ah_ + ao;
        const char* pAl = (const char*)Al_ + ao;
        size_t bo = ((size_t)woff + (size_t)c * Nfull * 64 + (size_t)n0g * 64) * 2;
        const char* pBh = (const char*)g_Wh + bo;
        const char* pBl = (const char*)g_Wl + bo;
        unsigned d = sb + (unsigned)(c & 1) * BUF;
        for (int i = tid * 16; i < 16384; i += NT * 16) {
            cp16(d + i, pAh + i);
            cp16(d + 16384 + i, pAl + i);
        }
        for (int i = tid * 16; i < NB * 128; i += NT * 16) {
            cp16(d + 32768 + i, pBh + i);
            cp16(d + 32768 + NB * 128 + i, pBl + i);
        }
        asm volatile("cp.async.commit_group;");
    };

    stage(0);
    if (nch > 1) stage(1);

    const int rowA = l & 15, kA = (l >> 4) * 8;
    const int nB = (l & 7) + ((l >> 4) & 1) * 8, kB = ((l >> 3) & 1) * 8;

    for (int c = 0; c < nch; c++) {
        if (c + 1 < nch) asm volatile("cp.async.wait_group 1;");
        else             asm volatile("cp.async.wait_group 0;");
        __syncthreads();

        const unsigned bb = sb + (unsigned)(c & 1) * BUF;
        const unsigned aH = bb, aL = bb + 16384;
        const unsigned bH = bb + 32768, bL = bb + 32768 + NB * 128;

#pragma unroll
        for (int ks = 0; ks < 4; ks++) {
            uint32_t ah[2][4], al[2][4];
#pragma unroll
            for (int mi = 0; mi < 2; mi++) {
                unsigned off = SWZ((m0 + mi * 16 + rowA) * 128 + (ks * 16 + kA) * 2);
                ldm4(ah[mi], aH + off);
                ldm4(al[mi], aL + off);
            }
            uint32_t bh[NJ][2], bl[NJ][2];
#pragma unroll
            for (int g = 0; g < NJ / 2; g++) {
                unsigned off = SWZ((n0l + g * 16 + nB) * 128 + (ks * 16 + kB) * 2);
                uint32_t r[4];
                ldm4(r, bH + off);
                bh[2 * g][0] = r[0]; bh[2 * g][1] = r[1];
                bh[2 * g + 1][0] = r[2]; bh[2 * g + 1][1] = r[3];
                ldm4(r, bL + off);
                bl[2 * g][0] = r[0]; bl[2 * g][1] = r[1];
                bl[2 * g + 1][0] = r[2]; bl[2 * g + 1][1] = r[3];
            }
#pragma unroll
            for (int mi = 0; mi < 2; mi++)
#pragma unroll
                for (int nj = 0; nj < NJ; nj++) {
                    mma16816(acc[mi][nj], ah[mi], bh[nj]);
                    mma16816(acc[mi][nj], al[mi], bh[nj]);
                    mma16816(acc[mi][nj], ah[mi], bl[nj]);
                }
        }
        if (c + 2 < nch) {
            __syncthreads();
            stage(c + 2);
        }
    }

    // ---- epilogue: bias + LeakyReLU + store ----
    const int rq = l >> 2, cq = (l & 3) * 2;
    const int nchO = Nfull >> 6;
#pragma unroll
    for (int mi = 0; mi < 2; mi++)
#pragma unroll
        for (int nj = 0; nj < NJ; nj++) {
            int cg = n0g + n0l + nj * 8 + cq;
            float b0 = g_Ba[boff + cg], b1 = g_Ba[boff + cg + 1];
            float v[4] = {acc[mi][nj][0] + b0, acc[mi][nj][1] + b1,
                          acc[mi][nj][2] + b0, acc[mi][nj][3] + b1};
            if (act) {
#pragma unroll
                for (int q = 0; q < 4; q++) v[q] = v[q] >= 0.f ? v[q] : 0.2f * v[q];
            }
            int r0 = m0 + mi * 16 + rq, r1 = r0 + 8;
            if (outmode == 1) {
                size_t m0r = (size_t)blockIdx.x * 128;
                *reinterpret_cast<float2*>(Of + (m0r + r0) * Nfull + cg) =
                    make_float2(v[0], v[1]);
                *reinterpret_cast<float2*>(Of + (m0r + r1) * Nfull + cg) =
                    make_float2(v[2], v[3]);
            } else {
                int chunk = cg >> 6, cc = cg & 63;
                size_t base = ((size_t)blockIdx.x * nchO + chunk) * 8192;
                __nv_bfloat162 h2, l2;
                int e0 = SWZ(r0 * 128 + cc * 2) >> 1;
                split2(v[0], v[1], h2, l2);
                *reinterpret_cast<__nv_bfloat162*>(Oh + base + e0) = h2;
                *reinterpret_cast<__nv_bfloat162*>(Ol + base + e0) = l2;
                int e1 = SWZ(r1 * 128 + cc * 2) >> 1;
                split2(v[2], v[3], h2, l2);
                *reinterpret_cast<__nv_bfloat162*>(Oh + base + e1) = h2;
                *reinterpret_cast<__nv_bfloat162*>(Ol + base + e1) = l2;
            }
        }
}

// ---------------- agg: per batch, agg = colsum(msg) - msg  -> swz bf16 pair
__global__ __launch_bounds__(128) void agg_k(const float* __restrict__ MSG,
                                             __nv_bfloat16* __restrict__ AGh,
                                             __nv_bfloat16* __restrict__ AGl) {
    int b = blockIdx.x, p = threadIdx.x;
    float2 v[NN];
    float sx = 0.f, sy = 0.f;
#pragma unroll
    for (int n = 0; n < NN; n++) {
        v[n] = *reinterpret_cast<const float2*>(MSG + ((size_t)b * NN + n) * 256 + 2 * p);
        sx += v[n].x; sy += v[n].y;
    }
    int chunk = p >> 5, cc = (2 * p) & 63;
#pragma unroll
    for (int n = 0; n < NN; n++) {
        size_t m = (size_t)b * NN + n;
        size_t tile = m >> 7; int rt = (int)(m & 127);
        size_t e = (tile * 4 + chunk) * 8192 + (SWZ(rt * 128 + cc * 2) >> 1);
        __nv_bfloat162 h2, l2;
        split2(sx - v[n].x, sy - v[n].y, h2, l2);
        *reinterpret_cast<__nv_bfloat162*>(AGh + e) = h2;
        *reinterpret_cast<__nv_bfloat162*>(AGl + e) = l2;
    }
}

// ---------------- attention per batch (fp32), ctx -> swz bf16 pair
#define ATT_FLOATS (5888 + 6144 + 5888 + 4416)
__global__ __launch_bounds__(NT) void att_k(const float* __restrict__ QH,
                                            const float* __restrict__ KH,
                                            const float* __restrict__ VH,
                                            __nv_bfloat16* __restrict__ CXh,
                                            __nv_bfloat16* __restrict__ CXl) {
    extern __shared__ float sm[];
    float* q = sm;
    float* kT = q + 5888;
    float* v = kT + 6144;
    float* S = v + 5888;
    const int tid = threadIdx.x, b = blockIdx.x;
    const size_t base = (size_t)b * NN * 256;

    for (int i = tid; i < 1472; i += NT) {
        reinterpret_cast<float4*>(q)[i] = reinterpret_cast<const float4*>(QH + base)[i];
        reinterpret_cast<float4*>(v)[i] = reinterpret_cast<const float4*>(VH + base)[i];
    }
    for (int i = tid; i < 5888; i += NT) {
        int m = i >> 8, c = i & 255;
        kT[c * 24 + m] = KH[base + (size_t)m * 256 + c];
    }
    __syncthreads();

    int w = tid >> 5, lane = tid & 31;
    for (int task = w; task < 184; task += 8) {
        int h = task / 23, n = task - h * 23;
        const float* qr = q + n * 256 + h * 32;
        float a = 0.f;
        if (lane < NN) {
#pragma unroll
            for (int d = 0; d < 32; d++) a += qr[d] * kT[(h * 32 + d) * 24 + lane];
        }
        float mx = (lane < NN) ? a : -1e30f;
#pragma unroll
        for (int o = 16; o; o >>= 1) mx = fmaxf(mx, __shfl_xor_sync(~0u, mx, o));
        float e = (lane < NN) ? __expf(a - mx) : 0.f;
        float s = e;
#pragma unroll
        for (int o = 16; o; o >>= 1) s += __shfl_xor_sync(~0u, s, o);
        if (lane < NN) S[h * 552 + n * 24 + lane] = e / s;
    }
    __syncthreads();

    for (int idx = tid; idx < NN * 128; idx += NT) {
        int n = idx >> 7, p = idx & 127, h = p >> 4;
        const float* Sr = S + h * 552 + n * 24;
        const float* vc = v + 2 * p;
        float ax = 0.f, ay = 0.f;
#pragma unroll
        for (int m = 0; m < NN; m++) {
            float s = Sr[m];
            ax += s * vc[m * 256];
            ay += s * vc[m * 256 + 1];
        }
        size_t mr = (size_t)b * NN + n;
        size_t tile = mr >> 7; int rt = (int)(mr & 127);
        size_t e = (tile * 4 + (p >> 5)) * 8192 + (SWZ(rt * 128 + ((2 * p) & 63) * 2) >> 1);
        __nv_bfloat162 h2, l2;
        split2(ax, ay, h2, l2);
        *reinterpret_cast<__nv_bfloat162*>(CXh + e) = h2;
        *reinterpret_cast<__nv_bfloat162*>(CXl + e) = l2;
    }
}

// ---------------- maxpool over nodes
__global__ __launch_bounds__(128) void pool_k(const float* __restrict__ CT2,
                                              __nv_bfloat16* __restrict__ PLh,
                                              __nv_bfloat16* __restrict__ PLl) {
    int b = blockIdx.x, p = threadIdx.x;
    float mx = -1e30f, my = -1e30f;
#pragma unroll
    for (int n = 0; n < NN; n++) {
        float2 t = *reinterpret_cast<const float2*>(CT2 + ((size_t)b * NN + n) * 256 + 2 * p);
        mx = fmaxf(mx, t.x); my = fmaxf(my, t.y);
    }
    size_t tile = b >> 7; int rt = b & 127;
    size_t e = (tile * 4 + (p >> 5)) * 8192 + (SWZ(rt * 128 + ((2 * p) & 63) * 2) >> 1);
    __nv_bfloat162 h2, l2;
    split2(mx, my, h2, l2);
    *reinterpret_cast<__nv_bfloat162*>(PLh + e) = h2;
    *reinterpret_cast<__nv_bfloat162*>(PLl + e) = l2;
}

// ---------------- head3: [B,64] -> [B,2]
__global__ __launch_bounds__(NT) void head3_k(const float* __restrict__ H2,
                                              float* __restrict__ out) {
    int b = blockIdx.x * NT + threadIdx.x;
    if (b >= BSZ) return;
    const float* h = H2 + (size_t)b * 64;
    float a0 = g_Ba[B3HO], a1 = g_Ba[B3HO + 1];
#pragma unroll
    for (int k = 0; k < 64; k++) {
        float x = h[k];
        a0 += x * g_Ba[W3HO + k];
        a1 += x * g_Ba[W3HO + 64 + k];
    }
    out[b * 2] = a0;
    out[b * 2 + 1] = a1;
}

// ---------------------------------------------------------------------------
extern "C" void kernel_launch(void* const* d_in, const int* in_sizes, int n_in,
                              void* d_out, int out_size) {
    const float* x   = (const float*)d_in[0];
    const float* mw1 = (const float*)d_in[1];
    const float* mb1 = (const float*)d_in[2];
    const float* mw2 = (const float*)d_in[3];
    const float* mb2 = (const float*)d_in[4];
    const float* mw3 = (const float*)d_in[5];
    const float* mb3 = (const float*)d_in[6];
    const float* qw  = (const float*)d_in[7];
    const float* qb  = (const float*)d_in[8];
    const float* kw  = (const float*)d_in[9];
    const float* kb  = (const float*)d_in[10];
    const float* vw  = (const float*)d_in[11];
    const float* vb  = (const float*)d_in[12];
    const float* inw = (const float*)d_in[13];
    const float* inb = (const float*)d_in[14];
    const float* ow  = (const float*)d_in[15];
    const float* ob  = (const float*)d_in[16];
    const float* ow1 = (const float*)d_in[17];
    const float* ob1 = (const float*)d_in[18];
    const float* ow2 = (const float*)d_in[19];
    const float* ob2 = (const float*)d_in[20];
    const float* ow3 = (const float*)d_in[21];
    const float* ob3 = (const float*)d_in[22];
    float* out = (float*)d_out;
    const float s = 0.17677669529663687f;

    // region base addresses (host-side symbol query; capture-safe)
    char *R0, *R1, *R2, *R3, *RS;
    cudaGetSymbolAddress((void**)&R0, g_R0);
    cudaGetSymbolAddress((void**)&R1, g_R1);
    cudaGetSymbolAddress((void**)&R2, g_R2);
    cudaGetSymbolAddress((void**)&R3, g_R3);
    cudaGetSymbolAddress((void**)&RS, g_RS);

    typedef __nv_bfloat16 bf;
    const size_t E64 = (size_t)MTOT * 64, E128 = (size_t)MTOT * 128,
                 E256 = (size_t)MTOT * 256;
    bf *XAh = (bf*)R0, *XAl = XAh + E64;            // phase 1 in
    bf *S1h = (bf*)R1, *S1l = S1h + E128;           // layer1 out
    bf *S2h = (bf*)R2, *S2l = S2h + E256;           // layer2 out
    float *MSG = (float*)R3;                        // layer3 out
    bf *AGh = (bf*)R0, *AGl = AGh + E256;           // agg out (XA dead)
    bf *Th  = (bf*)R1, *Tl  = Th + E256;            // conv temps (S1 dead)
    float *QH = (float*)R2;                         // (S2 dead)
    float *KH = (float*)R3;                         // (MSG dead)
    float *VH = (float*)R0;                         // (AG dead)
    bf *CXh = (bf*)R1, *CXl = CXh + E256;           // (T dead)
    float *CT2 = (float*)R2;                        // (QH dead)
    bf *PLh = (bf*)(RS + RS_PLH), *PLl = (bf*)(RS + RS_PLL);
    bf *H1h = (bf*)(RS + RS_H1H), *H1l = (bf*)(RS + RS_H1L);
    float *H2 = (float*)(RS + RS_H2);

    prep_w<<<32, 256>>>(mw1, 128, 7, 1, 1.f, W1OFF);
    prep_w<<<64, 256>>>(mw2, 256, 128, 2, 1.f, W2OFF);
    prep_w<<<128, 256>>>(mw3, 256, 256, 4, 1.f, W3OFF);
    prep_w<<<128, 256>>>(qw, 256, 256, 4, 1.f, QWOFF);
    prep_w<<<128, 256>>>(kw, 256, 256, 4, 1.f, KWOFF);
    prep_w<<<128, 256>>>(vw, 256, 256, 4, 1.f, VWOFF);
    prep_w<<<128, 256>>>(inw, 256, 256, 4, s, WQOFF);
    prep_w<<<128, 256>>>(inw + 65536, 256, 256, 4, 1.f, WKOFF);
    prep_w<<<128, 256>>>(inw + 131072, 256, 256, 4, 1.f, WVOFF);
    prep_w<<<128, 256>>>(ow, 256, 256, 4, 1.f, OWOFF);
    prep_w<<<64, 256>>>(ow1, 128, 256, 4, 1.f, O1OFF);
    prep_w<<<32, 256>>>(ow2, 64, 128, 2, 1.f, O2OFF);
    prep_bias<<<1, 256>>>(mb1, mb2, mb3, qb, kb, vb, inb, ob, ob1, ob2, ow3, ob3);
    prep_x<<<512, 256>>>(x, XAh, XAl);

    const int SM128 = 1024 + 2 * (32768 + 128 * 256);  // 132096
    const int SM64  = 1024 + 2 * (32768 + 64 * 256);   //  99328
    cudaFuncSetAttribute(gemm_hmma<128>,
                         cudaFuncAttributeMaxDynamicSharedMemorySize, SM128);
    cudaFuncSetAttribute(gemm_hmma<64>,
                         cudaFuncAttributeMaxDynamicSharedMemorySize, SM64);
    cudaFuncSetAttribute(att_k, cudaFuncAttributeMaxDynamicSharedMemorySize,
                         ATT_FLOATS * 4);

    dim3 G1(MTOT / 128, 1), G2(MTOT / 128, 2), GH(BSZ / 128, 1);

    gemm_hmma<128><<<G1, NT, SM128>>>(XAh, XAl, 1, W1OFF, 128, B1O, 1, 0,
                                      S1h, S1l, nullptr);
    gemm_hmma<128><<<G2, NT, SM128>>>(S1h, S1l, 2, W2OFF, 256, B2O, 1, 0,
                                      S2h, S2l, nullptr);
    gemm_hmma<128><<<G2, NT, SM128>>>(S2h, S2l, 4, W3OFF, 256, B3O, 0, 1,
                                      nullptr, nullptr, MSG);
    agg_k<<<BSZ, 128>>>(MSG, AGh, AGl);
    gemm_hmma<128><<<G2, NT, SM128>>>(AGh, AGl, 4, QWOFF, 256, QBO, 1, 0,
                                      Th, Tl, nullptr);
    gemm_hmma<128><<<G2, NT, SM128>>>(Th, Tl, 4, WQOFF, 256, BQO, 0, 1,
                                      nullptr, nullptr, QH);
    gemm_hmma<128><<<G2, NT, SM128>>>(AGh, AGl, 4, KWOFF, 256, KBO, 1, 0,
                                      Th, Tl, nullptr);
    gemm_hmma<128><<<G2, NT, SM128>>>(Th, Tl, 4, WKOFF, 256, BKO, 0, 1,
                                      nullptr, nullptr, KH);
    gemm_hmma<128><<<G2, NT, SM128>>>(AGh, AGl, 4, VWOFF, 256, VBO, 1, 0,
                                      Th, Tl, nullptr);
    gemm_hmma<128><<<G2, NT, SM128>>>(Th, Tl, 4, WVOFF, 256, BVO, 0, 1,
                                      nullptr, nullptr, VH);
    att_k<<<BSZ, NT, ATT_FLOATS * 4>>>(QH, KH, VH, CXh, CXl);
    gemm_hmma<128><<<G2, NT, SM128>>>(CXh, CXl, 4, OWOFF, 256, OBO, 0, 1,
                                      nullptr, nullptr, CT2);
    pool_k<<<BSZ, 128>>>(CT2, PLh, PLl);
    gemm_hmma<128><<<GH, NT, SM128>>>(PLh, PLl, 4, O1OFF, 128, OB1O, 1, 0,
                                      H1h, H1l, nullptr);
    gemm_hmma<64><<<GH, NT, SM64>>>(H1h, H1l, 2, O2OFF, 64, OB2O, 1, 1,
                                    nullptr, nullptr, H2);
    head3_k<<<BSZ / NT, NT>>>(H2, out);
}

// round 7
// speedup vs baseline: 5.4034x; 1.0547x over previous
#include <cuda_runtime.h>
#include <cuda_bf16.h>
#include <cstdint>

#define NN 23
#define BSZ 16384
#define MTOT (BSZ * NN)          // 376832 = 2944*128
#define NT 256
#define SWZ(o) ((o) ^ (((o) >> 3) & 0x70))

// ---------------- 4 big aliased regions + 1 small region -------------------
#define REGB ((size_t)MTOT * 256 * 4)      // 385,875,968
__device__ __align__(128) char g_R0[REGB];
__device__ __align__(128) char g_R1[REGB];
__device__ __align__(128) char g_R2[REGB];
__device__ __align__(128) char g_R3[REGB];
#define RS_PLH 0
#define RS_PLL ((size_t)BSZ * 256 * 2)
#define RS_H1H ((size_t)BSZ * 256 * 4)
#define RS_H1L (RS_H1H + (size_t)BSZ * 128 * 2)
#define RS_H2  (RS_H1H + (size_t)BSZ * 128 * 4)
#define RS_SZ  (RS_H2 + (size_t)BSZ * 64 * 4)
__device__ __align__(128) char g_RS[RS_SZ];

// ---------------- weight arena (pre-swizzled chunk images), elem offsets
#define W1OFF 0
#define W2OFF 8192
#define W3OFF 40960
#define QWOFF 106496
#define KWOFF 172032
#define VWOFF 237568
#define WQOFF 303104
#define WKOFF 368640
#define WVOFF 434176
#define OWOFF 499712
#define O1OFF 565248
#define O2OFF 598016
#define WSZ   606208
__device__ __align__(16) __nv_bfloat16 g_Wh[WSZ];
__device__ __align__(16) __nv_bfloat16 g_Wl[WSZ];

// bias arena (f32) + head3 weights
#define B1O 0
#define B2O 128
#define B3O 384
#define QBO 640
#define KBO 896
#define VBO 1152
#define BQO 1408
#define BKO 1664
#define BVO 1920
#define OBO 2176
#define OB1O 2432
#define OB2O 2560
#define W3HO 2624
#define B3HO 2752
__device__ float g_Ba[2816];

// ---------------- helpers
__device__ __forceinline__ unsigned smem_u32(const void* p) {
    return (unsigned)__cvta_generic_to_shared(p);
}
__device__ __forceinline__ void cp16(unsigned d, const void* s) {
    asm volatile("cp.async.cg.shared.global [%0], [%1], 16;" :: "r"(d), "l"(s));
}
__device__ __forceinline__ void ldm4(uint32_t* r, unsigned a) {
    asm volatile("ldmatrix.sync.aligned.m8n8.x4.shared.b16 {%0,%1,%2,%3}, [%4];"
                 : "=r"(r[0]), "=r"(r[1]), "=r"(r[2]), "=r"(r[3]) : "r"(a));
}
__device__ __forceinline__ void mma16816(float* c, const uint32_t* a,
                                         const uint32_t* b) {
    asm volatile(
        "mma.sync.aligned.m16n8k16.row.col.f32.bf16.bf16.f32 "
        "{%0,%1,%2,%3},{%4,%5,%6,%7},{%8,%9},{%0,%1,%2,%3};"
        : "+f"(c[0]), "+f"(c[1]), "+f"(c[2]), "+f"(c[3])
        : "r"(a[0]), "r"(a[1]), "r"(a[2]), "r"(a[3]), "r"(b[0]), "r"(b[1]));
}
__device__ __forceinline__ void split2(float a, float b,
                                       __nv_bfloat162& h2, __nv_bfloat162& l2) {
    __nv_bfloat16 ah = __float2bfloat16(a), bh = __float2bfloat16(b);
    h2 = __halves2bfloat162(ah, bh);
    l2 = __halves2bfloat162(__float2bfloat16(a - __bfloat162float(ah)),
                            __float2bfloat16(b - __bfloat162float(bh)));
}

// ---------------- merged weight prep: 13 segments in one launch ------------
struct PrepAll {
    const float* src[13];
    int O[13], K[13], nch[13];
    float scale[13];
    int off[13];
};
__global__ void prep_w_all(PrepAll pa) {
    int seg = blockIdx.y;
    const float* __restrict__ src = pa.src[seg];
    int O = pa.O[seg], K = pa.K[seg], nch = pa.nch[seg], off = pa.off[seg];
    float scale = pa.scale[seg];
    int tot = nch * O * 64;
    for (int e = blockIdx.x * blockDim.x + threadIdx.x; e < tot;
         e += gridDim.x * blockDim.x) {
        int kc = e / (O * 64), rem = e - kc * O * 64;
        int r = rem >> 6, kk = rem & 63, k = kc * 64 + kk;
        float v = (k < K) ? src[r * K + k] * scale : 0.f;
        __nv_bfloat16 h = __float2bfloat16(v);
        int dst = off + kc * O * 64 + (SWZ(r * 128 + kk * 2) >> 1);
        g_Wh[dst] = h;
        g_Wl[dst] = __float2bfloat16(v - __bfloat162float(h));
    }
}
__global__ void prep_x(const float* __restrict__ x,
                       __nv_bfloat16* __restrict__ XAh,
                       __nv_bfloat16* __restrict__ XAl) {
    for (size_t e = (size_t)blockIdx.x * blockDim.x + threadIdx.x;
         e < (size_t)MTOT * 64; e += (size_t)gridDim.x * blockDim.x) {
        size_t m = e >> 6;
        int c = (int)(e & 63);
        float v = (c < 7) ? x[m * 7 + c] : 0.f;
        size_t tile = m >> 7;
        int rt = (int)(m & 127);
        size_t dst = tile * 8192 + (SWZ(rt * 128 + c * 2) >> 1);
        __nv_bfloat16 h = __float2bfloat16(v);
        XAh[dst] = h;
        XAl[dst] = __float2bfloat16(v - __bfloat162float(h));
    }
}
__global__ void prep_bias(const float* b1, const float* b2, const float* b3,
                          const float* qb, const float* kb, const float* vb,
                          const float* inb, const float* ob, const float* ob1,
                          const float* ob2, const float* ow3, const float* ob3) {
    const float s = 0.17677669529663687f;
    int t = threadIdx.x;
    for (int i = t; i < 128; i += 256) g_Ba[B1O + i] = b1[i];
    for (int i = t; i < 256; i += 256) g_Ba[B2O + i] = b2[i];
    for (int i = t; i < 256; i += 256) g_Ba[B3O + i] = b3[i];
    for (int i = t; i < 256; i += 256) g_Ba[QBO + i] = qb[i];
    for (int i = t; i < 256; i += 256) g_Ba[KBO + i] = kb[i];
    for (int i = t; i < 256; i += 256) g_Ba[VBO + i] = vb[i];
    for (int i = t; i < 256; i += 256) g_Ba[BQO + i] = inb[i] * s;
    for (int i = t; i < 256; i += 256) g_Ba[BKO + i] = inb[256 + i];
    for (int i = t; i < 256; i += 256) g_Ba[BVO + i] = inb[512 + i];
    for (int i = t; i < 256; i += 256) g_Ba[OBO + i] = ob[i];
    for (int i = t; i < 128; i += 256) g_Ba[OB1O + i] = ob1[i];
    for (int i = t; i < 64;  i += 256) g_Ba[OB2O + i] = ob2[i];
    for (int i = t; i < 128; i += 256) g_Ba[W3HO + i] = ow3[i];
    for (int i = t; i < 2;   i += 256) g_Ba[B3HO + i] = ob3[i];
}

// ---------------------------------------------------------------------------
// HMMA GEMM: CTA tile M=128 x 64, K = nch*64, 3-term bf16 split, occupancy 2.
// grid = (Nfull/64, MTOT/128): n-split fastest -> adjacent CTAs share A in L2.
// smem stage: Ah 16K | Al 16K | Bh 8K | Bl 8K  (48K), double-buffered.
// ---------------------------------------------------------------------------
#define BUFB 49152
#define GSMEM (1024 + 2 * BUFB)   // 99328
__global__ void __launch_bounds__(NT, 2) gemm_hmma(
    const __nv_bfloat16* __restrict__ Ah_, const __nv_bfloat16* __restrict__ Al_,
    int nch, int woff, int Nfull, int boff, int act, int outmode,
    __nv_bfloat16* __restrict__ Oh, __nv_bfloat16* __restrict__ Ol,
    float* __restrict__ Of) {
    extern __shared__ char smem[];
    const unsigned sb = smem_u32(smem) + 1024;
    const int tid = threadIdx.x, w = tid >> 5, l = tid & 31;
    const int m0 = (w >> 1) * 32, n0l = (w & 1) * 32;
    const int n0g = blockIdx.x * 64;
    const int mt = blockIdx.y;

    float acc[2][4][4];
#pragma unroll
    for (int mi = 0; mi < 2; mi++)
#pragma unroll
        for (int nj = 0; nj < 4; nj++)
#pragma unroll
            for (int q = 0; q < 4; q++) acc[mi][nj][q] = 0.f;

    auto stage = [&](int c) {
        size_t ao = ((size_t)mt * nch + c) * 16384;
        const char* pAh = (const char*)Ah_ + ao;
        const char* pAl = (const char*)Al_ + ao;
        size_t bo = ((size_t)woff + (size_t)c * Nfull * 64 + (size_t)n0g * 64) * 2;
        const char* pBh = (const char*)g_Wh + bo;
        const char* pBl = (const char*)g_Wl + bo;
        unsigned d = sb + (unsigned)(c & 1) * BUFB;
        for (int i = tid * 16; i < 16384; i += NT * 16) {
            cp16(d + i, pAh + i);
            cp16(d + 16384 + i, pAl + i);
        }
        for (int i = tid * 16; i < 8192; i += NT * 16) {
            cp16(d + 32768 + i, pBh + i);
            cp16(d + 40960 + i, pBl + i);
        }
        asm volatile("cp.async.commit_group;");
    };

    stage(0);
    if (nch > 1) stage(1);

    const int rowA = l & 15, kA = (l >> 4) * 8;
    const int nB = (l & 7) + ((l >> 4) & 1) * 8, kB = ((l >> 3) & 1) * 8;

    for (int c = 0; c < nch; c++) {
        if (c + 1 < nch) asm volatile("cp.async.wait_group 1;");
        else             asm volatile("cp.async.wait_group 0;");
        __syncthreads();

        const unsigned bb = sb + (unsigned)(c & 1) * BUFB;
        const unsigned aH = bb, aL = bb + 16384;
        const unsigned bH = bb + 32768, bL = bb + 40960;

#pragma unroll
        for (int ks = 0; ks < 4; ks++) {
            uint32_t ah[2][4], al[2][4];
#pragma unroll
            for (int mi = 0; mi < 2; mi++) {
                unsigned off = SWZ((m0 + mi * 16 + rowA) * 128 + (ks * 16 + kA) * 2);
                ldm4(ah[mi], aH + off);
                ldm4(al[mi], aL + off);
            }
#pragma unroll
            for (int g = 0; g < 2; g++) {
                unsigned off = SWZ((n0l + g * 16 + nB) * 128 + (ks * 16 + kB) * 2);
                uint32_t rh[4], rl[4];
                ldm4(rh, bH + off);
                ldm4(rl, bL + off);
#pragma unroll
                for (int mi = 0; mi < 2; mi++) {
                    mma16816(acc[mi][2 * g], ah[mi], rh);
                    mma16816(acc[mi][2 * g], al[mi], rh);
                    mma16816(acc[mi][2 * g], ah[mi], rl);
                    mma16816(acc[mi][2 * g + 1], ah[mi], rh + 2);
                    mma16816(acc[mi][2 * g + 1], al[mi], rh + 2);
                    mma16816(acc[mi][2 * g + 1], ah[mi], rl + 2);
                }
            }
        }
        if (c + 2 < nch) {
            __syncthreads();
            stage(c + 2);
        }
    }

    // ---- epilogue: bias + LeakyReLU + store ----
    const int rq = l >> 2, cq = (l & 3) * 2;
    const int nchO = Nfull >> 6;
#pragma unroll
    for (int mi = 0; mi < 2; mi++)
#pragma unroll
        for (int nj = 0; nj < 4; nj++) {
            int cg = n0g + n0l + nj * 8 + cq;
            float b0 = g_Ba[boff + cg], b1 = g_Ba[boff + cg + 1];
            float v[4] = {acc[mi][nj][0] + b0, acc[mi][nj][1] + b1,
                          acc[mi][nj][2] + b0, acc[mi][nj][3] + b1};
            if (act) {
#pragma unroll
                for (int q = 0; q < 4; q++) v[q] = v[q] >= 0.f ? v[q] : 0.2f * v[q];
            }
            int r0 = m0 + mi * 16 + rq, r1 = r0 + 8;
            if (outmode == 1) {
                size_t m0r = (size_t)mt * 128;
                *reinterpret_cast<float2*>(Of + (m0r + r0) * Nfull + cg) =
                    make_float2(v[0], v[1]);
                *reinterpret_cast<float2*>(Of + (m0r + r1) * Nfull + cg) =
                    make_float2(v[2], v[3]);
            } else {
                int chunk = cg >> 6, cc = cg & 63;
                size_t base = ((size_t)mt * nchO + chunk) * 8192;
                __nv_bfloat162 h2, l2;
                int e0 = SWZ(r0 * 128 + cc * 2) >> 1;
                split2(v[0], v[1], h2, l2);
                *reinterpret_cast<__nv_bfloat162*>(Oh + base + e0) = h2;
                *reinterpret_cast<__nv_bfloat162*>(Ol + base + e0) = l2;
                int e1 = SWZ(r1 * 128 + cc * 2) >> 1;
                split2(v[2], v[3], h2, l2);
                *reinterpret_cast<__nv_bfloat162*>(Oh + base + e1) = h2;
                *reinterpret_cast<__nv_bfloat162*>(Ol + base + e1) = l2;
            }
        }
}

// ---------------- agg: per batch, agg = colsum(msg) - msg  -> swz bf16 pair
__global__ __launch_bounds__(128) void agg_k(const float* __restrict__ MSG,
                                             __nv_bfloat16* __restrict__ AGh,
                                             __nv_bfloat16* __restrict__ AGl) {
    int b = blockIdx.x, p = threadIdx.x;
    float2 v[NN];
    float sx = 0.f, sy = 0.f;
#pragma unroll
    for (int n = 0; n < NN; n++) {
        v[n] = *reinterpret_cast<const float2*>(MSG + ((size_t)b * NN + n) * 256 + 2 * p);
        sx += v[n].x; sy += v[n].y;
    }
    int chunk = p >> 5, cc = (2 * p) & 63;
#pragma unroll
    for (int n = 0; n < NN; n++) {
        size_t m = (size_t)b * NN + n;
        size_t tile = m >> 7; int rt = (int)(m & 127);
        size_t e = (tile * 4 + chunk) * 8192 + (SWZ(rt * 128 + cc * 2) >> 1);
        __nv_bfloat162 h2, l2;
        split2(sx - v[n].x, sy - v[n].y, h2, l2);
        *reinterpret_cast<__nv_bfloat162*>(AGh + e) = h2;
        *reinterpret_cast<__nv_bfloat162*>(AGl + e) = l2;
    }
}

// ---------------- attention per batch (fp32), ctx -> swz bf16 pair
#define ATT_FLOATS (5888 + 6144 + 5888 + 4416)
__global__ __launch_bounds__(NT) void att_k(const float* __restrict__ QH,
                                            const float* __restrict__ KH,
                                            const float* __restrict__ VH,
                                            __nv_bfloat16* __restrict__ CXh,
                                            __nv_bfloat16* __restrict__ CXl) {
    extern __shared__ float sm[];
    float* q = sm;
    float* kT = q + 5888;
    float* v = kT + 6144;
    float* S = v + 5888;
    const int tid = threadIdx.x, b = blockIdx.x;
    const size_t base = (size_t)b * NN * 256;

    for (int i = tid; i < 1472; i += NT) {
        reinterpret_cast<float4*>(q)[i] = reinterpret_cast<const float4*>(QH + base)[i];
        reinterpret_cast<float4*>(v)[i] = reinterpret_cast<const float4*>(VH + base)[i];
    }
    for (int i = tid; i < 5888; i += NT) {
        int m = i >> 8, c = i & 255;
        kT[c * 24 + m] = KH[base + (size_t)m * 256 + c];
    }
    __syncthreads();

    int w = tid >> 5, lane = tid & 31;
    for (int task = w; task < 184; task += 8) {
        int h = task / 23, n = task - h * 23;
        const float* qr = q + n * 256 + h * 32;
        float a = 0.f;
        if (lane < NN) {
#pragma unroll
            for (int d = 0; d < 32; d++) a += qr[d] * kT[(h * 32 + d) * 24 + lane];
        }
        float mx = (lane < NN) ? a : -1e30f;
#pragma unroll
        for (int o = 16; o; o >>= 1) mx = fmaxf(mx, __shfl_xor_sync(~0u, mx, o));
        float e = (lane < NN) ? __expf(a - mx) : 0.f;
        float s = e;
#pragma unroll
        for (int o = 16; o; o >>= 1) s += __shfl_xor_sync(~0u, s, o);
        if (lane < NN) S[h * 552 + n * 24 + lane] = e / s;
    }
    __syncthreads();

    for (int idx = tid; idx < NN * 128; idx += NT) {
        int n = idx >> 7, p = idx & 127, h = p >> 4;
        const float* Sr = S + h * 552 + n * 24;
        const float* vc = v + 2 * p;
        float ax = 0.f, ay = 0.f;
#pragma unroll
        for (int m = 0; m < NN; m++) {
            float s = Sr[m];
            ax += s * vc[m * 256];
            ay += s * vc[m * 256 + 1];
        }
        size_t mr = (size_t)b * NN + n;
        size_t tile = mr >> 7; int rt = (int)(mr & 127);
        size_t e = (tile * 4 + (p >> 5)) * 8192 + (SWZ(rt * 128 + ((2 * p) & 63) * 2) >> 1);
        __nv_bfloat162 h2, l2;
        split2(ax, ay, h2, l2);
        *reinterpret_cast<__nv_bfloat162*>(CXh + e) = h2;
        *reinterpret_cast<__nv_bfloat162*>(CXl + e) = l2;
    }
}

// ---------------- maxpool over nodes
__global__ __launch_bounds__(128) void pool_k(const float* __restrict__ CT2,
                                              __nv_bfloat16* __restrict__ PLh,
                                              __nv_bfloat16* __restrict__ PLl) {
    int b = blockIdx.x, p = threadIdx.x;
    float mx = -1e30f, my = -1e30f;
#pragma unroll
    for (int n = 0; n < NN; n++) {
        float2 t = *reinterpret_cast<const float2*>(CT2 + ((size_t)b * NN + n) * 256 + 2 * p);
        mx = fmaxf(mx, t.x); my = fmaxf(my, t.y);
    }
    size_t tile = b >> 7; int rt = b & 127;
    size_t e = (tile * 4 + (p >> 5)) * 8192 + (SWZ(rt * 128 + ((2 * p) & 63) * 2) >> 1);
    __nv_bfloat162 h2, l2;
    split2(mx, my, h2, l2);
    *reinterpret_cast<__nv_bfloat162*>(PLh + e) = h2;
    *reinterpret_cast<__nv_bfloat162*>(PLl + e) = l2;
}

// ---------------- head3: [B,64] -> [B,2]
__global__ __launch_bounds__(NT) void head3_k(const float* __restrict__ H2,
                                              float* __restrict__ out) {
    int b = blockIdx.x * NT + threadIdx.x;
    if (b >= BSZ) return;
    const float* h = H2 + (size_t)b * 64;
    float a0 = g_Ba[B3HO], a1 = g_Ba[B3HO + 1];
#pragma unroll
    for (int k = 0; k < 64; k++) {
        float x = h[k];
        a0 += x * g_Ba[W3HO + k];
        a1 += x * g_Ba[W3HO + 64 + k];
    }
    out[b * 2] = a0;
    out[b * 2 + 1] = a1;
}

// ---------------------------------------------------------------------------
extern "C" void kernel_launch(void* const* d_in, const int* in_sizes, int n_in,
                              void* d_out, int out_size) {
    const float* x   = (const float*)d_in[0];
    const float* mw1 = (const float*)d_in[1];
    const float* mb1 = (const float*)d_in[2];
    const float* mw2 = (const float*)d_in[3];
    const float* mb2 = (const float*)d_in[4];
    const float* mw3 = (const float*)d_in[5];
    const float* mb3 = (const float*)d_in[6];
    const float* qw  = (const float*)d_in[7];
    const float* qb  = (const float*)d_in[8];
    const float* kw  = (const float*)d_in[9];
    const float* kb  = (const float*)d_in[10];
    const float* vw  = (const float*)d_in[11];
    const float* vb  = (const float*)d_in[12];
    const float* inw = (const float*)d_in[13];
    const float* inb = (const float*)d_in[14];
    const float* ow  = (const float*)d_in[15];
    const float* ob  = (const float*)d_in[16];
    const float* ow1 = (const float*)d_in[17];
    const float* ob1 = (const float*)d_in[18];
    const float* ow2 = (const float*)d_in[19];
    const float* ob2 = (const float*)d_in[20];
    const float* ow3 = (const float*)d_in[21];
    const float* ob3 = (const float*)d_in[22];
    float* out = (float*)d_out;
    const float s = 0.17677669529663687f;

    char *R0, *R1, *R2, *R3, *RS;
    cudaGetSymbolAddress((void**)&R0, g_R0);
    cudaGetSymbolAddress((void**)&R1, g_R1);
    cudaGetSymbolAddress((void**)&R2, g_R2);
    cudaGetSymbolAddress((void**)&R3, g_R3);
    cudaGetSymbolAddress((void**)&RS, g_RS);

    typedef __nv_bfloat16 bf;
    const size_t E64 = (size_t)MTOT * 64, E128 = (size_t)MTOT * 128,
                 E256 = (size_t)MTOT * 256;
    bf *XAh = (bf*)R0, *XAl = XAh + E64;
    bf *S1h = (bf*)R1, *S1l = S1h + E128;
    bf *S2h = (bf*)R2, *S2l = S2h + E256;
    float *MSG = (float*)R3;
    bf *AGh = (bf*)R0, *AGl = AGh + E256;
    bf *Th  = (bf*)R1, *Tl  = Th + E256;
    float *QH = (float*)R2;
    float *KH = (float*)R3;
    float *VH = (float*)R0;
    bf *CXh = (bf*)R1, *CXl = CXh + E256;
    float *CT2 = (float*)R2;
    bf *PLh = (bf*)(RS + RS_PLH), *PLl = (bf*)(RS + RS_PLL);
    bf *H1h = (bf*)(RS + RS_H1H), *H1l = (bf*)(RS + RS_H1L);
    float *H2 = (float*)(RS + RS_H2);

    // merged weight prep
    PrepAll pa;
    const float* srcs[13] = {mw1, mw2, mw3, qw, kw, vw, inw, inw + 65536,
                             inw + 131072, ow, ow1, ow2, nullptr};
    int Os[13]   = {128, 256, 256, 256, 256, 256, 256, 256, 256, 256, 128, 64, 1};
    int Ks[13]   = {7, 128, 256, 256, 256, 256, 256, 256, 256, 256, 256, 128, 1};
    int nchs[13] = {1, 2, 4, 4, 4, 4, 4, 4, 4, 4, 4, 2, 0};
    float scs[13] = {1.f, 1.f, 1.f, 1.f, 1.f, 1.f, s, 1.f, 1.f, 1.f, 1.f, 1.f, 0.f};
    int offs[13] = {W1OFF, W2OFF, W3OFF, QWOFF, KWOFF, VWOFF, WQOFF, WKOFF,
                    WVOFF, OWOFF, O1OFF, O2OFF, 0};
    for (int i = 0; i < 13; i++) {
        pa.src[i] = srcs[i] ? srcs[i] : mw1;
        pa.O[i] = Os[i]; pa.K[i] = Ks[i];
        pa.nch[i] = nchs[i]; pa.scale[i] = scs[i]; pa.off[i] = offs[i];
    }
    prep_w_all<<<dim3(64, 12), 256>>>(pa);
    prep_bias<<<1, 256>>>(mb1, mb2, mb3, qb, kb, vb, inb, ob, ob1, ob2, ow3, ob3);
    prep_x<<<512, 256>>>(x, XAh, XAl);

    cudaFuncSetAttribute(gemm_hmma,
                         cudaFuncAttributeMaxDynamicSharedMemorySize, GSMEM);
    cudaFuncSetAttribute(att_k, cudaFuncAttributeMaxDynamicSharedMemorySize,
                         ATT_FLOATS * 4);

    const int MT = MTOT / 128;  // 2944
    dim3 G128(2, MT), G256(4, MT), GH1(2, BSZ / 128), GH2(1, BSZ / 128);

    gemm_hmma<<<G128, NT, GSMEM>>>(XAh, XAl, 1, W1OFF, 128, B1O, 1, 0,
                                   S1h, S1l, nullptr);
    gemm_hmma<<<G256, NT, GSMEM>>>(S1h, S1l, 2, W2OFF, 256, B2O, 1, 0,
                                   S2h, S2l, nullptr);
    gemm_hmma<<<G256, NT, GSMEM>>>(S2h, S2l, 4, W3OFF, 256, B3O, 0, 1,
                                   nullptr, nullptr, MSG);
    agg_k<<<BSZ, 128>>>(MSG, AGh, AGl);
    gemm_hmma<<<G256, NT, GSMEM>>>(AGh, AGl, 4, QWOFF, 256, QBO, 1, 0,
                                   Th, Tl, nullptr);
    gemm_hmma<<<G256, NT, GSMEM>>>(Th, Tl, 4, WQOFF, 256, BQO, 0, 1,
                                   nullptr, nullptr, QH);
    gemm_hmma<<<G256, NT, GSMEM>>>(AGh, AGl, 4, KWOFF, 256, KBO, 1, 0,
                                   Th, Tl, nullptr);
    gemm_hmma<<<G256, NT, GSMEM>>>(Th, Tl, 4, WKOFF, 256, BKO, 0, 1,
                                   nullptr, nullptr, KH);
    gemm_hmma<<<G256, NT, GSMEM>>>(AGh, AGl, 4, VWOFF, 256, VBO, 1, 0,
                                   Th, Tl, nullptr);
    gemm_hmma<<<G256, NT, GSMEM>>>(Th, Tl, 4, WVOFF, 256, BVO, 0, 1,
                                   nullptr, nullptr, VH);
    att_k<<<BSZ, NT, ATT_FLOATS * 4>>>(QH, KH, VH, CXh, CXl);
    gemm_hmma<<<G256, NT, GSMEM>>>(CXh, CXl, 4, OWOFF, 256, OBO, 0, 1,
                                   nullptr, nullptr, CT2);
    pool_k<<<BSZ, 128>>>(CT2, PLh, PLl);
    gemm_hmma<<<GH1, NT, GSMEM>>>(PLh, PLl, 4, O1OFF, 128, OB1O, 1, 0,
                                  H1h, H1l, nullptr);
    gemm_hmma<<<GH2, NT, GSMEM>>>(H1h, H1l, 2, O2OFF, 64, OB2O, 1, 1,
                                  nullptr, nullptr, H2);
    head3_k<<<BSZ / NT, NT>>>(H2, out);
}

// round 8
// speedup vs baseline: 5.8586x; 1.0842x over previous
#include <cuda_runtime.h>
#include <cuda_bf16.h>
#include <cstdint>

#define NN 23
#define BSZ 16384
#define MTOT (BSZ * NN)          // 376832 = 2944*128
#define NT 256
#define SWZ(o) ((o) ^ (((o) >> 3) & 0x70))

// ---------------- 4 big aliased regions + 1 small region -------------------
#define REGB ((size_t)MTOT * 256 * 4)      // 385,875,968
__device__ __align__(128) char g_R0[REGB];
__device__ __align__(128) char g_R1[REGB];
__device__ __align__(128) char g_R2[REGB];
__device__ __align__(128) char g_R3[REGB];
#define RS_PLH 0
#define RS_PLL ((size_t)BSZ * 256 * 2)
#define RS_H1H ((size_t)BSZ * 256 * 4)
#define RS_H1L (RS_H1H + (size_t)BSZ * 128 * 2)
#define RS_H2  (RS_H1H + (size_t)BSZ * 128 * 4)
#define RS_SZ  (RS_H2 + (size_t)BSZ * 64 * 4)
__device__ __align__(128) char g_RS[RS_SZ];

// ---------------- weight arena (pre-swizzled chunk images), elem offsets
#define W1OFF 0
#define W2OFF 8192
#define FQOFF 40960              // fused folded QKV: O=768, nch=4 -> 196608
#define WQOFF 237568
#define WKOFF 303104
#define WVOFF 368640
#define OWOFF 434176
#define O1OFF 499712
#define O2OFF 532480
#define WSZ   540672
__device__ __align__(16) __nv_bfloat16 g_Wh[WSZ];
__device__ __align__(16) __nv_bfloat16 g_Wl[WSZ];

// bias arena (f32) + head3 weights + folded qkv bias (768 @ FQB)
#define B1O 0
#define B2O 128
#define BQO 1408
#define BKO 1664
#define BVO 1920
#define OBO 2176
#define OB1O 2432
#define OB2O 2560
#define W3HO 2624
#define B3HO 2752
#define FQB 3072
__device__ float g_Ba[4096];

// ---------------- helpers
__device__ __forceinline__ unsigned smem_u32(const void* p) {
    return (unsigned)__cvta_generic_to_shared(p);
}
__device__ __forceinline__ void cp16(unsigned d, const void* s) {
    asm volatile("cp.async.cg.shared.global [%0], [%1], 16;" :: "r"(d), "l"(s));
}
__device__ __forceinline__ void ldm4(uint32_t* r, unsigned a) {
    asm volatile("ldmatrix.sync.aligned.m8n8.x4.shared.b16 {%0,%1,%2,%3}, [%4];"
                 : "=r"(r[0]), "=r"(r[1]), "=r"(r[2]), "=r"(r[3]) : "r"(a));
}
__device__ __forceinline__ void mma16816(float* c, const uint32_t* a,
                                         const uint32_t* b) {
    asm volatile(
        "mma.sync.aligned.m16n8k16.row.col.f32.bf16.bf16.f32 "
        "{%0,%1,%2,%3},{%4,%5,%6,%7},{%8,%9},{%0,%1,%2,%3};"
        : "+f"(c[0]), "+f"(c[1]), "+f"(c[2]), "+f"(c[3])
        : "r"(a[0]), "r"(a[1]), "r"(a[2]), "r"(a[3]), "r"(b[0]), "r"(b[1]));
}
__device__ __forceinline__ void split2(float a, float b,
                                       __nv_bfloat162& h2, __nv_bfloat162& l2) {
    __nv_bfloat16 ah = __float2bfloat16(a), bh = __float2bfloat16(b);
    h2 = __halves2bfloat162(ah, bh);
    l2 = __halves2bfloat162(__float2bfloat16(a - __bfloat162float(ah)),
                            __float2bfloat16(b - __bfloat162float(bh)));
}

// ---------------- fold kernels: F_g = w_g @ W3 ; fb = b_g + 22*w_g@b3 ------
__global__ void fold_k(const float* __restrict__ qw, const float* __restrict__ kw,
                       const float* __restrict__ vw, const float* __restrict__ w3,
                       float* __restrict__ scr) {
    int r = blockIdx.x, g = blockIdx.y, t = threadIdx.x;
    __shared__ float row[256];
    const float* w = g == 0 ? qw : (g == 1 ? kw : vw);
    row[t] = w[r * 256 + t];
    __syncthreads();
    float a = 0.f;
#pragma unroll 8
    for (int j = 0; j < 256; j++) a += row[j] * w3[j * 256 + t];
    scr[((size_t)(g * 256 + r)) * 256 + t] = a;
}
__global__ void fold_b(const float* qw, const float* kw, const float* vw,
                       const float* qb, const float* kb, const float* vb,
                       const float* b3) {
    int o = blockIdx.x * 256 + threadIdx.x;
    int g = o >> 8, r = o & 255;
    const float* w = g == 0 ? qw : (g == 1 ? kw : vw);
    const float* b = g == 0 ? qb : (g == 1 ? kb : vb);
    float a = 0.f;
#pragma unroll 8
    for (int j = 0; j < 256; j++) a += w[r * 256 + j] * b3[j];
    g_Ba[FQB + o] = b[r] + 22.f * a;
}

// ---------------- merged weight prep: 9 segments in one launch -------------
struct PrepAll {
    const float* src[9];
    int O[9], K[9], nch[9];
    float scale[9];
    int off[9];
};
__global__ void prep_w_all(PrepAll pa) {
    int seg = blockIdx.y;
    const float* __restrict__ src = pa.src[seg];
    int O = pa.O[seg], K = pa.K[seg], nch = pa.nch[seg], off = pa.off[seg];
    float scale = pa.scale[seg];
    int tot = nch * O * 64;
    for (int e = blockIdx.x * blockDim.x + threadIdx.x; e < tot;
         e += gridDim.x * blockDim.x) {
        int kc = e / (O * 64), rem = e - kc * O * 64;
        int r = rem >> 6, kk = rem & 63, k = kc * 64 + kk;
        float v = (k < K) ? src[(size_t)r * K + k] * scale : 0.f;
        __nv_bfloat16 h = __float2bfloat16(v);
        int dst = off + kc * O * 64 + (SWZ(r * 128 + kk * 2) >> 1);
        g_Wh[dst] = h;
        g_Wl[dst] = __float2bfloat16(v - __bfloat162float(h));
    }
}
__global__ void prep_x(const float* __restrict__ x,
                       __nv_bfloat16* __restrict__ XAh,
                       __nv_bfloat16* __restrict__ XAl) {
    for (size_t e = (size_t)blockIdx.x * blockDim.x + threadIdx.x;
         e < (size_t)MTOT * 64; e += (size_t)gridDim.x * blockDim.x) {
        size_t m = e >> 6;
        int c = (int)(e & 63);
        float v = (c < 7) ? x[m * 7 + c] : 0.f;
        size_t tile = m >> 7;
        int rt = (int)(m & 127);
        size_t dst = tile * 8192 + (SWZ(rt * 128 + c * 2) >> 1);
        __nv_bfloat16 h = __float2bfloat16(v);
        XAh[dst] = h;
        XAl[dst] = __float2bfloat16(v - __bfloat162float(h));
    }
}
__global__ void prep_bias(const float* b1, const float* b2,
                          const float* inb, const float* ob, const float* ob1,
                          const float* ob2, const float* ow3, const float* ob3) {
    const float s = 0.17677669529663687f;
    int t = threadIdx.x;
    for (int i = t; i < 128; i += 256) g_Ba[B1O + i] = b1[i];
    for (int i = t; i < 256; i += 256) g_Ba[B2O + i] = b2[i];
    for (int i = t; i < 256; i += 256) g_Ba[BQO + i] = inb[i] * s;
    for (int i = t; i < 256; i += 256) g_Ba[BKO + i] = inb[256 + i];
    for (int i = t; i < 256; i += 256) g_Ba[BVO + i] = inb[512 + i];
    for (int i = t; i < 256; i += 256) g_Ba[OBO + i] = ob[i];
    for (int i = t; i < 128; i += 256) g_Ba[OB1O + i] = ob1[i];
    for (int i = t; i < 64;  i += 256) g_Ba[OB2O + i] = ob2[i];
    for (int i = t; i < 128; i += 256) g_Ba[W3HO + i] = ow3[i];
    for (int i = t; i < 2;   i += 256) g_Ba[B3HO + i] = ob3[i];
}

// ---------------------------------------------------------------------------
// HMMA GEMM: CTA tile M=128 x 64, K = nch*64, 3-term bf16 split, occupancy 2.
// Output can span up to 3 buffers of 256 cols each (fused QKV: Nfull=768).
// ---------------------------------------------------------------------------
#define BUFB 49152
#define GSMEM (1024 + 2 * BUFB)   // includes 1024 alignment slack
__global__ void __launch_bounds__(NT, 2) gemm_hmma(
    const __nv_bfloat16* __restrict__ Ah_, const __nv_bfloat16* __restrict__ Al_,
    int nch, int woff, int Nfull, int boff, int act, int outmode,
    __nv_bfloat16* __restrict__ Oh, __nv_bfloat16* __restrict__ Ol,
    __nv_bfloat16* __restrict__ Oh1, __nv_bfloat16* __restrict__ Ol1,
    __nv_bfloat16* __restrict__ Oh2, __nv_bfloat16* __restrict__ Ol2,
    float* __restrict__ Of) {
    extern __shared__ char smem[];
    const unsigned sb = (smem_u32(smem) + 1023u) & ~1023u;  // 1024-aligned
    const int tid = threadIdx.x, w = tid >> 5, l = tid & 31;
    const int m0 = (w >> 1) * 32, n0l = (w & 1) * 32;
    const int n0g = blockIdx.x * 64;
    const int mt = blockIdx.y;

    float acc[2][4][4];
#pragma unroll
    for (int mi = 0; mi < 2; mi++)
#pragma unroll
        for (int nj = 0; nj < 4; nj++)
#pragma unroll
            for (int q = 0; q < 4; q++) acc[mi][nj][q] = 0.f;

    auto stage = [&](int c) {
        size_t ao = ((size_t)mt * nch + c) * 16384;
        const char* pAh = (const char*)Ah_ + ao;
        const char* pAl = (const char*)Al_ + ao;
        size_t bo = ((size_t)woff + (size_t)c * Nfull * 64 + (size_t)n0g * 64) * 2;
        const char* pBh = (const char*)g_Wh + bo;
        const char* pBl = (const char*)g_Wl + bo;
        unsigned d = sb + (unsigned)(c & 1) * BUFB;
        for (int i = tid * 16; i < 16384; i += NT * 16) {
            cp16(d + i, pAh + i);
            cp16(d + 16384 + i, pAl + i);
        }
        for (int i = tid * 16; i < 8192; i += NT * 16) {
            cp16(d + 32768 + i, pBh + i);
            cp16(d + 40960 + i, pBl + i);
        }
        asm volatile("cp.async.commit_group;");
    };

    stage(0);
    if (nch > 1) stage(1);

    const int rowA = l & 15, kA = (l >> 4) * 8;
    const int nB = (l & 7) + ((l >> 4) & 1) * 8, kB = ((l >> 3) & 1) * 8;
    const unsigned offA0 = SWZ((m0 + rowA) * 128 + kA * 2);
    const unsigned offA1 = SWZ((m0 + 16 + rowA) * 128 + kA * 2);
    const unsigned offB0 = SWZ((n0l + nB) * 128 + kB * 2);
    const unsigned offB1 = SWZ((n0l + 16 + nB) * 128 + kB * 2);

    for (int c = 0; c < nch; c++) {
        if (c + 1 < nch) asm volatile("cp.async.wait_group 1;");
        else             asm volatile("cp.async.wait_group 0;");
        __syncthreads();

        const unsigned bb = sb + (unsigned)(c & 1) * BUFB;
        const unsigned aH0 = bb + offA0, aH1 = bb + offA1;
        const unsigned aL0 = aH0 + 16384, aL1 = aH1 + 16384;
        const unsigned bH0 = bb + 32768 + offB0, bH1 = bb + 32768 + offB1;
        const unsigned bL0 = bH0 + 8192, bL1 = bH1 + 8192;

#pragma unroll
        for (int ks = 0; ks < 4; ks++) {
            const unsigned kx = (unsigned)(ks << 5);  // XOR-advance (bits 5-6)
            uint32_t ah[2][4], al[2][4];
            ldm4(ah[0], aH0 ^ kx);
            ldm4(al[0], aL0 ^ kx);
            ldm4(ah[1], aH1 ^ kx);
            ldm4(al[1], aL1 ^ kx);
#pragma unroll
            for (int g = 0; g < 2; g++) {
                uint32_t rh[4], rl[4];
                ldm4(rh, (g ? bH1 : bH0) ^ kx);
                ldm4(rl, (g ? bL1 : bL0) ^ kx);
#pragma unroll
                for (int mi = 0; mi < 2; mi++) {
                    mma16816(acc[mi][2 * g], ah[mi], rh);
                    mma16816(acc[mi][2 * g], al[mi], rh);
                    mma16816(acc[mi][2 * g], ah[mi], rl);
                    mma16816(acc[mi][2 * g + 1], ah[mi], rh + 2);
                    mma16816(acc[mi][2 * g + 1], al[mi], rh + 2);
                    mma16816(acc[mi][2 * g + 1], ah[mi], rl + 2);
                }
            }
        }
        if (c + 2 < nch) {
            __syncthreads();
            stage(c + 2);
        }
    }

    // ---- epilogue: bias + LeakyReLU + store (grp-routed for fused QKV) ----
    const int rq = l >> 2, cq = (l & 3) * 2;
    const int nchO = (Nfull >= 256 ? 4 : (Nfull >> 6));
#pragma unroll
    for (int mi = 0; mi < 2; mi++)
#pragma unroll
        for (int nj = 0; nj < 4; nj++) {
            int cg = n0g + n0l + nj * 8 + cq;
            float b0 = g_Ba[boff + cg], b1 = g_Ba[boff + cg + 1];
            float v[4] = {acc[mi][nj][0] + b0, acc[mi][nj][1] + b1,
                          acc[mi][nj][2] + b0, acc[mi][nj][3] + b1};
            if (act) {
#pragma unroll
                for (int q = 0; q < 4; q++) v[q] = v[q] >= 0.f ? v[q] : 0.2f * v[q];
            }
            int r0 = m0 + mi * 16 + rq, r1 = r0 + 8;
            if (outmode == 1) {
                size_t m0r = (size_t)mt * 128;
                *reinterpret_cast<float2*>(Of + (m0r + r0) * Nfull + cg) =
                    make_float2(v[0], v[1]);
                *reinterpret_cast<float2*>(Of + (m0r + r1) * Nfull + cg) =
                    make_float2(v[2], v[3]);
            } else {
                int grp = cg >> 8, cgl = cg & 255;
                __nv_bfloat16* OH = grp == 0 ? Oh : (grp == 1 ? Oh1 : Oh2);
                __nv_bfloat16* OL = grp == 0 ? Ol : (grp == 1 ? Ol1 : Ol2);
                int chunk = cgl >> 6, cc = cgl & 63;
                size_t base = ((size_t)mt * nchO + chunk) * 8192;
                __nv_bfloat162 h2, l2;
                int e0 = SWZ(r0 * 128 + cc * 2) >> 1;
                split2(v[0], v[1], h2, l2);
                *reinterpret_cast<__nv_bfloat162*>(OH + base + e0) = h2;
                *reinterpret_cast<__nv_bfloat162*>(OL + base + e0) = l2;
                int e1 = SWZ(r1 * 128 + cc * 2) >> 1;
                split2(v[2], v[3], h2, l2);
                *reinterpret_cast<__nv_bfloat162*>(OH + base + e1) = h2;
                *reinterpret_cast<__nv_bfloat162*>(OL + base + e1) = l2;
            }
        }
}

// ---------------- agg in h2-space: G_n = sum_m h2_m - h2_n (pair images) ---
__global__ __launch_bounds__(128) void agg2_k(const __nv_bfloat16* __restrict__ S2h,
                                              const __nv_bfloat16* __restrict__ S2l,
                                              __nv_bfloat16* __restrict__ Gh,
                                              __nv_bfloat16* __restrict__ Gl) {
    int b = blockIdx.x, p = threadIdx.x;
    int chunk = p >> 5, cc = (2 * p) & 63;
    float2 v[NN];
    float sx = 0.f, sy = 0.f;
    size_t eo[NN];
#pragma unroll
    for (int n = 0; n < NN; n++) {
        size_t m = (size_t)b * NN + n;
        size_t tile = m >> 7; int rt = (int)(m & 127);
        size_t e = (tile * 4 + chunk) * 8192 + (SWZ(rt * 128 + cc * 2) >> 1);
        eo[n] = e;
        __nv_bfloat162 h2 = *reinterpret_cast<const __nv_bfloat162*>(S2h + e);
        __nv_bfloat162 l2 = *reinterpret_cast<const __nv_bfloat162*>(S2l + e);
        v[n] = make_float2(__bfloat162float(h2.x) + __bfloat162float(l2.x),
                           __bfloat162float(h2.y) + __bfloat162float(l2.y));
        sx += v[n].x; sy += v[n].y;
    }
#pragma unroll
    for (int n = 0; n < NN; n++) {
        __nv_bfloat162 h2, l2;
        split2(sx - v[n].x, sy - v[n].y, h2, l2);
        *reinterpret_cast<__nv_bfloat162*>(Gh + eo[n]) = h2;
        *reinterpret_cast<__nv_bfloat162*>(Gl + eo[n]) = l2;
    }
}

// ---------------- attention per batch (fp32), ctx -> swz bf16 pair
#define ATT_FLOATS (5888 + 6144 + 5888 + 4416)
__global__ __launch_bounds__(NT) void att_k(const float* __restrict__ QH,
                                            const float* __restrict__ KH,
                                            const float* __restrict__ VH,
                                            __nv_bfloat16* __restrict__ CXh,
                                            __nv_bfloat16* __restrict__ CXl) {
    extern __shared__ float sm[];
    float* q = sm;
    float* kT = q + 5888;
    float* v = kT + 6144;
    float* S = v + 5888;
    const int tid = threadIdx.x, b = blockIdx.x;
    const size_t base = (size_t)b * NN * 256;

    for (int i = tid; i < 1472; i += NT) {
        reinterpret_cast<float4*>(q)[i] = reinterpret_cast<const float4*>(QH + base)[i];
        reinterpret_cast<float4*>(v)[i] = reinterpret_cast<const float4*>(VH + base)[i];
    }
    for (int i = tid; i < 5888; i += NT) {
        int m = i >> 8, c = i & 255;
        kT[c * 24 + m] = KH[base + (size_t)m * 256 + c];
    }
    __syncthreads();

    int w = tid >> 5, lane = tid & 31;
    for (int task = w; task < 184; task += 8) {
        int h = task / 23, n = task - h * 23;
        const float* qr = q + n * 256 + h * 32;
        float a = 0.f;
        if (lane < NN) {
#pragma unroll
            for (int d = 0; d < 32; d++) a += qr[d] * kT[(h * 32 + d) * 24 + lane];
        }
        float mx = (lane < NN) ? a : -1e30f;
#pragma unroll
        for (int o = 16; o; o >>= 1) mx = fmaxf(mx, __shfl_xor_sync(~0u, mx, o));
        float e = (lane < NN) ? __expf(a - mx) : 0.f;
        float s = e;
#pragma unroll
        for (int o = 16; o; o >>= 1) s += __shfl_xor_sync(~0u, s, o);
        if (lane < NN) S[h * 552 + n * 24 + lane] = e / s;
    }
    __syncthreads();

    for (int idx = tid; idx < NN * 128; idx += NT) {
        int n = idx >> 7, p = idx & 127, h = p >> 4;
        const float* Sr = S + h * 552 + n * 24;
        const float* vc = v + 2 * p;
        float ax = 0.f, ay = 0.f;
#pragma unroll
        for (int m = 0; m < NN; m++) {
            float s = Sr[m];
            ax += s * vc[m * 256];
            ay += s * vc[m * 256 + 1];
        }
        size_t mr = (size_t)b * NN + n;
        size_t tile = mr >> 7; int rt = (int)(mr & 127);
        size_t e = (tile * 4 + (p >> 5)) * 8192 + (SWZ(rt * 128 + ((2 * p) & 63) * 2) >> 1);
        __nv_bfloat162 h2, l2;
        split2(ax, ay, h2, l2);
        *reinterpret_cast<__nv_bfloat162*>(CXh + e) = h2;
        *reinterpret_cast<__nv_bfloat162*>(CXl + e) = l2;
    }
}

// ---------------- maxpool over nodes
__global__ __launch_bounds__(128) void pool_k(const float* __restrict__ CT2,
                                              __nv_bfloat16* __restrict__ PLh,
                                              __nv_bfloat16* __restrict__ PLl) {
    int b = blockIdx.x, p = threadIdx.x;
    float mx = -1e30f, my = -1e30f;
#pragma unroll
    for (int n = 0; n < NN; n++) {
        float2 t = *reinterpret_cast<const float2*>(CT2 + ((size_t)b * NN + n) * 256 + 2 * p);
        mx = fmaxf(mx, t.x); my = fmaxf(my, t.y);
    }
    size_t tile = b >> 7; int rt = b & 127;
    size_t e = (tile * 4 + (p >> 5)) * 8192 + (SWZ(rt * 128 + ((2 * p) & 63) * 2) >> 1);
    __nv_bfloat162 h2, l2;
    split2(mx, my, h2, l2);
    *reinterpret_cast<__nv_bfloat162*>(PLh + e) = h2;
    *reinterpret_cast<__nv_bfloat162*>(PLl + e) = l2;
}

// ---------------- head3: [B,64] -> [B,2]
__global__ __launch_bounds__(NT) void head3_k(const float* __restrict__ H2,
                                              float* __restrict__ out) {
    int b = blockIdx.x * NT + threadIdx.x;
    if (b >= BSZ) return;
    const float* h = H2 + (size_t)b * 64;
    float a0 = g_Ba[B3HO], a1 = g_Ba[B3HO + 1];
#pragma unroll
    for (int k = 0; k < 64; k++) {
        float x = h[k];
        a0 += x * g_Ba[W3HO + k];
        a1 += x * g_Ba[W3HO + 64 + k];
    }
    out[b * 2] = a0;
    out[b * 2 + 1] = a1;
}

// ---------------------------------------------------------------------------
extern "C" void kernel_launch(void* const* d_in, const int* in_sizes, int n_in,
                              void* d_out, int out_size) {
    const float* x   = (const float*)d_in[0];
    const float* mw1 = (const float*)d_in[1];
    const float* mb1 = (const float*)d_in[2];
    const float* mw2 = (const float*)d_in[3];
    const float* mb2 = (const float*)d_in[4];
    const float* mw3 = (const float*)d_in[5];
    const float* mb3 = (const float*)d_in[6];
    const float* qw  = (const float*)d_in[7];
    const float* qb  = (const float*)d_in[8];
    const float* kw  = (const float*)d_in[9];
    const float* kb  = (const float*)d_in[10];
    const float* vw  = (const float*)d_in[11];
    const float* vb  = (const float*)d_in[12];
    const float* inw = (const float*)d_in[13];
    const float* inb = (const float*)d_in[14];
    const float* ow  = (const float*)d_in[15];
    const float* ob  = (const float*)d_in[16];
    const float* ow1 = (const float*)d_in[17];
    const float* ob1 = (const float*)d_in[18];
    const float* ow2 = (const float*)d_in[19];
    const float* ob2 = (const float*)d_in[20];
    const float* ow3 = (const float*)d_in[21];
    const float* ob3 = (const float*)d_in[22];
    float* out = (float*)d_out;
    const float s = 0.17677669529663687f;

    char *R0, *R1, *R2, *R3, *RS;
    cudaGetSymbolAddress((void**)&R0, g_R0);
    cudaGetSymbolAddress((void**)&R1, g_R1);
    cudaGetSymbolAddress((void**)&R2, g_R2);
    cudaGetSymbolAddress((void**)&R3, g_R3);
    cudaGetSymbolAddress((void**)&RS, g_RS);

    typedef __nv_bfloat16 bf;
    const size_t E64 = (size_t)MTOT * 64, E128 = (size_t)MTOT * 128,
                 E256 = (size_t)MTOT * 256;
    bf *XAh = (bf*)R0, *XAl = XAh + E64;
    bf *S1h = (bf*)R1, *S1l = S1h + E128;
    bf *S2h = (bf*)R2, *S2l = S2h + E256;
    bf *Gh  = (bf*)R0, *Gl  = Gh + E256;      // XA dead
    bf *Tqh = (bf*)R1, *Tql = Tqh + E256;     // S1 dead
    bf *Tkh = (bf*)R2, *Tkl = Tkh + E256;     // S2 dead (after agg2)
    bf *Tvh = (bf*)R3, *Tvl = Tvh + E256;
    float *QH = (float*)R0;                   // G dead
    float *KH = (float*)R1;                   // Tq dead
    float *VH = (float*)R2;                   // Tk dead
    bf *CXh = (bf*)R3, *CXl = CXh + E256;     // Tv dead
    float *CT2 = (float*)R0;                  // QH dead
    bf *PLh = (bf*)(RS + RS_PLH), *PLl = (bf*)(RS + RS_PLL);
    bf *H1h = (bf*)(RS + RS_H1H), *H1l = (bf*)(RS + RS_H1L);
    float *H2 = (float*)(RS + RS_H2);
    float *scr = (float*)R3;                  // fold scratch (prep-time only)

    // ---- prep: fold W3 into QKV, pack weights/biases, pack x ----
    fold_k<<<dim3(256, 3), 256>>>(qw, kw, vw, mw3, scr);
    fold_b<<<3, 256>>>(qw, kw, vw, qb, kb, vb, mb3);
    PrepAll pa;
    const float* srcs[9] = {mw1, mw2, scr, inw, inw + 65536, inw + 131072,
                            ow, ow1, ow2};
    int Os[9]   = {128, 256, 768, 256, 256, 256, 256, 128, 64};
    int Ks[9]   = {7, 128, 256, 256, 256, 256, 256, 256, 128};
    int nchs[9] = {1, 2, 4, 4, 4, 4, 4, 4, 2};
    float scs[9] = {1.f, 1.f, 1.f, s, 1.f, 1.f, 1.f, 1.f, 1.f};
    int offs[9] = {W1OFF, W2OFF, FQOFF, WQOFF, WKOFF, WVOFF, OWOFF, O1OFF, O2OFF};
    for (int i = 0; i < 9; i++) {
        pa.src[i] = srcs[i]; pa.O[i] = Os[i]; pa.K[i] = Ks[i];
        pa.nch[i] = nchs[i]; pa.scale[i] = scs[i]; pa.off[i] = offs[i];
    }
    prep_w_all<<<dim3(64, 9), 256>>>(pa);
    prep_bias<<<1, 256>>>(mb1, mb2, inb, ob, ob1, ob2, ow3, ob3);
    prep_x<<<512, 256>>>(x, XAh, XAl);

    cudaFuncSetAttribute(gemm_hmma,
                         cudaFuncAttributeMaxDynamicSharedMemorySize, GSMEM);
    cudaFuncSetAttribute(att_k, cudaFuncAttributeMaxDynamicSharedMemorySize,
                         ATT_FLOATS * 4);

    const int MT = MTOT / 128;  // 2944
    dim3 G128(2, MT), G256(4, MT), G768(12, MT), GH1(2, BSZ / 128),
         GH2(1, BSZ / 128);
    bf* Z = nullptr;

    gemm_hmma<<<G128, NT, GSMEM>>>(XAh, XAl, 1, W1OFF, 128, B1O, 1, 0,
                                   S1h, S1l, Z, Z, Z, Z, nullptr);
    gemm_hmma<<<G256, NT, GSMEM>>>(S1h, S1l, 2, W2OFF, 256, B2O, 1, 0,
                                   S2h, S2l, Z, Z, Z, Z, nullptr);
    agg2_k<<<BSZ, 128>>>(S2h, S2l, Gh, Gl);
    gemm_hmma<<<G768, NT, GSMEM>>>(Gh, Gl, 4, FQOFF, 768, FQB, 1, 0,
                                   Tqh, Tql, Tkh, Tkl, Tvh, Tvl, nullptr);
    gemm_hmma<<<G256, NT, GSMEM>>>(Tqh, Tql, 4, WQOFF, 256, BQO, 0, 1,
                                   Z, Z, Z, Z, Z, Z, QH);
    gemm_hmma<<<G256, NT, GSMEM>>>(Tkh, Tkl, 4, WKOFF, 256, BKO, 0, 1,
                                   Z, Z, Z, Z, Z, Z, KH);
    gemm_hmma<<<G256, NT, GSMEM>>>(Tvh, Tvl, 4, WVOFF, 256, BVO, 0, 1,
                                   Z, Z, Z, Z, Z, Z, VH);
    att_k<<<BSZ, NT, ATT_FLOATS * 4>>>(QH, KH, VH, CXh, CXl);
    gemm_hmma<<<G256, NT, GSMEM>>>(CXh, CXl, 4, OWOFF, 256, OBO, 0, 1,
                                   Z, Z, Z, Z, Z, Z, CT2);
    pool_k<<<BSZ, 128>>>(CT2, PLh, PLl);
    gemm_hmma<<<GH1, NT, GSMEM>>>(PLh, PLl, 4, O1OFF, 128, OB1O, 1, 0,
                                  H1h, H1l, Z, Z, Z, Z, nullptr);
    gemm_hmma<<<GH2, NT, GSMEM>>>(H1h, H1l, 2, O2OFF, 64, OB2O, 1, 1,
                                  Z, Z, Z, Z, Z, Z, H2);
    head3_k<<<BSZ / NT, NT>>>(H2, out);
}

// round 9
// speedup vs baseline: 5.9275x; 1.0118x over previous
#include <cuda_runtime.h>
#include <cuda_bf16.h>
#include <cstdint>

#define NN 23
#define BSZ 16384
#define MTOT (BSZ * NN)          // 376832 = 2944*128
#define NT 256
#define SWZ(o) ((o) ^ (((o) >> 3) & 0x70))

// ---------------- 4 big aliased regions + 1 small region -------------------
#define REGB ((size_t)MTOT * 256 * 4)      // 385,875,968
__device__ __align__(128) char g_R0[REGB];
__device__ __align__(128) char g_R1[REGB];
__device__ __align__(128) char g_R2[REGB];
__device__ __align__(128) char g_R3[REGB];
#define RS_PLH 0
#define RS_PLL ((size_t)BSZ * 256 * 2)
#define RS_H1H ((size_t)BSZ * 256 * 4)
#define RS_H1L (RS_H1H + (size_t)BSZ * 128 * 2)
#define RS_H2  (RS_H1H + (size_t)BSZ * 128 * 4)
#define RS_SZ  (RS_H2 + (size_t)BSZ * 64 * 4)
__device__ __align__(128) char g_RS[RS_SZ];

// ---------------- weight arena (pre-swizzled chunk images), elem offsets
#define W1OFF 0
#define W2OFF 8192
#define FQOFF 40960              // fused folded QKV: O=768, nch=4 -> 196608
#define WQOFF 237568
#define WKOFF 303104
#define WVOFF 368640
#define OWOFF 434176
#define O1OFF 499712
#define O2OFF 532480
#define WSZ   540672
__device__ __align__(16) __nv_bfloat16 g_Wh[WSZ];
__device__ __align__(16) __nv_bfloat16 g_Wl[WSZ];

// bias arena (f32) + head3 weights + folded qkv bias (768 @ FQB)
#define B1O 0
#define B2O 128
#define BQO 1408
#define BKO 1664
#define BVO 1920
#define OBO 2176
#define OB1O 2432
#define OB2O 2560
#define W3HO 2624
#define B3HO 2752
#define FQB 3072
__device__ float g_Ba[4096];

// ---------------- helpers
__device__ __forceinline__ unsigned smem_u32(const void* p) {
    return (unsigned)__cvta_generic_to_shared(p);
}
__device__ __forceinline__ void cp16(unsigned d, const void* s) {
    asm volatile("cp.async.cg.shared.global [%0], [%1], 16;" :: "r"(d), "l"(s));
}
__device__ __forceinline__ void ldm4(uint32_t* r, unsigned a) {
    asm volatile("ldmatrix.sync.aligned.m8n8.x4.shared.b16 {%0,%1,%2,%3}, [%4];"
                 : "=r"(r[0]), "=r"(r[1]), "=r"(r[2]), "=r"(r[3]) : "r"(a));
}
__device__ __forceinline__ void mma16816(float* c, const uint32_t* a,
                                         const uint32_t* b) {
    asm volatile(
        "mma.sync.aligned.m16n8k16.row.col.f32.bf16.bf16.f32 "
        "{%0,%1,%2,%3},{%4,%5,%6,%7},{%8,%9},{%0,%1,%2,%3};"
        : "+f"(c[0]), "+f"(c[1]), "+f"(c[2]), "+f"(c[3])
        : "r"(a[0]), "r"(a[1]), "r"(a[2]), "r"(a[3]), "r"(b[0]), "r"(b[1]));
}
__device__ __forceinline__ void split2(float a, float b,
                                       __nv_bfloat162& h2, __nv_bfloat162& l2) {
    __nv_bfloat16 ah = __float2bfloat16(a), bh = __float2bfloat16(b);
    h2 = __halves2bfloat162(ah, bh);
    l2 = __halves2bfloat162(__float2bfloat16(a - __bfloat162float(ah)),
                            __float2bfloat16(b - __bfloat162float(bh)));
}

// ---------------- fold kernels: F_g = w_g @ W3 ; fb = b_g + 22*w_g@b3 ------
__global__ void fold_k(const float* __restrict__ qw, const float* __restrict__ kw,
                       const float* __restrict__ vw, const float* __restrict__ w3,
                       float* __restrict__ scr) {
    int r = blockIdx.x, g = blockIdx.y, t = threadIdx.x;
    __shared__ float row[256];
    const float* w = g == 0 ? qw : (g == 1 ? kw : vw);
    row[t] = w[r * 256 + t];
    __syncthreads();
    float a = 0.f;
#pragma unroll 8
    for (int j = 0; j < 256; j++) a += row[j] * w3[j * 256 + t];
    scr[((size_t)(g * 256 + r)) * 256 + t] = a;
}
__global__ void fold_b(const float* qw, const float* kw, const float* vw,
                       const float* qb, const float* kb, const float* vb,
                       const float* b3) {
    int o = blockIdx.x * 256 + threadIdx.x;
    int g = o >> 8, r = o & 255;
    const float* w = g == 0 ? qw : (g == 1 ? kw : vw);
    const float* b = g == 0 ? qb : (g == 1 ? kb : vb);
    float a = 0.f;
#pragma unroll 8
    for (int j = 0; j < 256; j++) a += w[r * 256 + j] * b3[j];
    g_Ba[FQB + o] = b[r] + 22.f * a;
}

// ---------------- merged weight prep: 9 segments in one launch -------------
struct PrepAll {
    const float* src[9];
    int O[9], K[9], nch[9];
    float scale[9];
    int off[9];
};
__global__ void prep_w_all(PrepAll pa) {
    int seg = blockIdx.y;
    const float* __restrict__ src = pa.src[seg];
    int O = pa.O[seg], K = pa.K[seg], nch = pa.nch[seg], off = pa.off[seg];
    float scale = pa.scale[seg];
    int tot = nch * O * 64;
    for (int e = blockIdx.x * blockDim.x + threadIdx.x; e < tot;
         e += gridDim.x * blockDim.x) {
        int kc = e / (O * 64), rem = e - kc * O * 64;
        int r = rem >> 6, kk = rem & 63, k = kc * 64 + kk;
        float v = (k < K) ? src[(size_t)r * K + k] * scale : 0.f;
        __nv_bfloat16 h = __float2bfloat16(v);
        int dst = off + kc * O * 64 + (SWZ(r * 128 + kk * 2) >> 1);
        g_Wh[dst] = h;
        g_Wl[dst] = __float2bfloat16(v - __bfloat162float(h));
    }
}
__global__ void prep_x(const float* __restrict__ x,
                       __nv_bfloat16* __restrict__ XAh,
                       __nv_bfloat16* __restrict__ XAl) {
    for (size_t e = (size_t)blockIdx.x * blockDim.x + threadIdx.x;
         e < (size_t)MTOT * 64; e += (size_t)gridDim.x * blockDim.x) {
        size_t m = e >> 6;
        int c = (int)(e & 63);
        float v = (c < 7) ? x[m * 7 + c] : 0.f;
        size_t tile = m >> 7;
        int rt = (int)(m & 127);
        size_t dst = tile * 8192 + (SWZ(rt * 128 + c * 2) >> 1);
        __nv_bfloat16 h = __float2bfloat16(v);
        XAh[dst] = h;
        XAl[dst] = __float2bfloat16(v - __bfloat162float(h));
    }
}
__global__ void prep_bias(const float* b1, const float* b2,
                          const float* inb, const float* ob, const float* ob1,
                          const float* ob2, const float* ow3, const float* ob3) {
    const float s = 0.17677669529663687f;
    int t = threadIdx.x;
    for (int i = t; i < 128; i += 256) g_Ba[B1O + i] = b1[i];
    for (int i = t; i < 256; i += 256) g_Ba[B2O + i] = b2[i];
    for (int i = t; i < 256; i += 256) g_Ba[BQO + i] = inb[i] * s;
    for (int i = t; i < 256; i += 256) g_Ba[BKO + i] = inb[256 + i];
    for (int i = t; i < 256; i += 256) g_Ba[BVO + i] = inb[512 + i];
    for (int i = t; i < 256; i += 256) g_Ba[OBO + i] = ob[i];
    for (int i = t; i < 128; i += 256) g_Ba[OB1O + i] = ob1[i];
    for (int i = t; i < 64;  i += 256) g_Ba[OB2O + i] = ob2[i];
    for (int i = t; i < 128; i += 256) g_Ba[W3HO + i] = ow3[i];
    for (int i = t; i < 2;   i += 256) g_Ba[B3HO + i] = ob3[i];
}

// ---------------------------------------------------------------------------
// HMMA GEMM: CTA tile M=128 x 64, K = nch*64, 3-term bf16 split, occupancy 2.
// blockIdx.z selects among up to 3 (A, Of, woff, boff) sets (fused in_proj).
// Epilogue stages C through smem, then writes fully coalesced.
// ---------------------------------------------------------------------------
#define BUFB 49152
#define GSMEM (1024 + 2 * BUFB)
__global__ void __launch_bounds__(NT, 2) gemm_hmma(
    const __nv_bfloat16* __restrict__ Ah_, const __nv_bfloat16* __restrict__ Al_,
    const __nv_bfloat16* __restrict__ Ah1_, const __nv_bfloat16* __restrict__ Al1_,
    const __nv_bfloat16* __restrict__ Ah2_, const __nv_bfloat16* __restrict__ Al2_,
    int nch, int woff, int wzs, int Nfull, int boff, int act, int outmode,
    __nv_bfloat16* __restrict__ Oh, __nv_bfloat16* __restrict__ Ol,
    __nv_bfloat16* __restrict__ Oh1, __nv_bfloat16* __restrict__ Ol1,
    __nv_bfloat16* __restrict__ Oh2, __nv_bfloat16* __restrict__ Ol2,
    float* __restrict__ Of, float* __restrict__ Of1, float* __restrict__ Of2) {
    extern __shared__ char smem[];
    const unsigned sb = (smem_u32(smem) + 1023u) & ~1023u;  // 1024-aligned
    char* scm = smem + (sb - smem_u32(smem));
    const int tid = threadIdx.x, w = tid >> 5, l = tid & 31;
    const int m0 = (w >> 1) * 32, n0l = (w & 1) * 32;
    const int n0g = blockIdx.x * 64;
    const int mt = blockIdx.y;
    const int z = blockIdx.z;
    const __nv_bfloat16* Ahp = z == 0 ? Ah_ : (z == 1 ? Ah1_ : Ah2_);
    const __nv_bfloat16* Alp = z == 0 ? Al_ : (z == 1 ? Al1_ : Al2_);
    float* Ofz = z == 0 ? Of : (z == 1 ? Of1 : Of2);
    const int woz = woff + z * wzs, boz = boff + z * 256;

    float acc[2][4][4];
#pragma unroll
    for (int mi = 0; mi < 2; mi++)
#pragma unroll
        for (int nj = 0; nj < 4; nj++)
#pragma unroll
            for (int q = 0; q < 4; q++) acc[mi][nj][q] = 0.f;

    auto stage = [&](int c) {
        size_t ao = ((size_t)mt * nch + c) * 16384;
        const char* pAh = (const char*)Ahp + ao;
        const char* pAl = (const char*)Alp + ao;
        size_t bo = ((size_t)woz + (size_t)c * Nfull * 64 + (size_t)n0g * 64) * 2;
        const char* pBh = (const char*)g_Wh + bo;
        const char* pBl = (const char*)g_Wl + bo;
        unsigned d = sb + (unsigned)(c & 1) * BUFB;
        for (int i = tid * 16; i < 16384; i += NT * 16) {
            cp16(d + i, pAh + i);
            cp16(d + 16384 + i, pAl + i);
        }
        for (int i = tid * 16; i < 8192; i += NT * 16) {
            cp16(d + 32768 + i, pBh + i);
            cp16(d + 40960 + i, pBl + i);
        }
        asm volatile("cp.async.commit_group;");
    };

    stage(0);
    if (nch > 1) stage(1);

    const int rowA = l & 15, kA = (l >> 4) * 8;
    const int nB = (l & 7) + ((l >> 4) & 1) * 8, kB = ((l >> 3) & 1) * 8;
    const unsigned offA0 = SWZ((m0 + rowA) * 128 + kA * 2);
    const unsigned offA1 = SWZ((m0 + 16 + rowA) * 128 + kA * 2);
    const unsigned offB0 = SWZ((n0l + nB) * 128 + kB * 2);
    const unsigned offB1 = SWZ((n0l + 16 + nB) * 128 + kB * 2);

    for (int c = 0; c < nch; c++) {
        if (c + 1 < nch) asm volatile("cp.async.wait_group 1;");
        else             asm volatile("cp.async.wait_group 0;");
        __syncthreads();

        const unsigned bb = sb + (unsigned)(c & 1) * BUFB;
        const unsigned aH0 = bb + offA0, aH1 = bb + offA1;
        const unsigned aL0 = aH0 + 16384, aL1 = aH1 + 16384;
        const unsigned bH0 = bb + 32768 + offB0, bH1 = bb + 32768 + offB1;
        const unsigned bL0 = bH0 + 8192, bL1 = bH1 + 8192;

#pragma unroll
        for (int ks = 0; ks < 4; ks++) {
            const unsigned kx = (unsigned)(ks << 5);  // XOR-advance (bits 5-6)
            uint32_t ah[2][4], al[2][4];
            ldm4(ah[0], aH0 ^ kx);
            ldm4(al[0], aL0 ^ kx);
            ldm4(ah[1], aH1 ^ kx);
            ldm4(al[1], aL1 ^ kx);
#pragma unroll
            for (int g = 0; g < 2; g++) {
                uint32_t rh[4], rl[4];
                ldm4(rh, (g ? bH1 : bH0) ^ kx);
                ldm4(rl, (g ? bL1 : bL0) ^ kx);
#pragma unroll
                for (int mi = 0; mi < 2; mi++) {
                    mma16816(acc[mi][2 * g], ah[mi], rh);
                    mma16816(acc[mi][2 * g], al[mi], rh);
                    mma16816(acc[mi][2 * g], ah[mi], rl);
                    mma16816(acc[mi][2 * g + 1], ah[mi], rh + 2);
                    mma16816(acc[mi][2 * g + 1], al[mi], rh + 2);
                    mma16816(acc[mi][2 * g + 1], ah[mi], rl + 2);
                }
            }
        }
        if (c + 2 < nch) {
            __syncthreads();
            stage(c + 2);
        }
    }

    // ---- epilogue: bias + LeakyReLU, smem-staged, coalesced stores ----
    __syncthreads();
    const int rq = l >> 2, cq = (l & 3) * 2;
    if (outmode == 0) {
#pragma unroll
        for (int mi = 0; mi < 2; mi++)
#pragma unroll
            for (int nj = 0; nj < 4; nj++) {
                int lc = n0l + nj * 8 + cq;
                int cg = n0g + lc;
                float b0 = g_Ba[boz + cg], b1 = g_Ba[boz + cg + 1];
                float v[4] = {acc[mi][nj][0] + b0, acc[mi][nj][1] + b1,
                              acc[mi][nj][2] + b0, acc[mi][nj][3] + b1};
                if (act) {
#pragma unroll
                    for (int q = 0; q < 4; q++)
                        v[q] = v[q] >= 0.f ? v[q] : 0.2f * v[q];
                }
                int r0 = m0 + mi * 16 + rq, r1 = r0 + 8;
                int e0 = SWZ(r0 * 128 + lc * 2), e1 = SWZ(r1 * 128 + lc * 2);
                __nv_bfloat162 h2, l2;
                split2(v[0], v[1], h2, l2);
                *reinterpret_cast<__nv_bfloat162*>(scm + e0) = h2;
                *reinterpret_cast<__nv_bfloat162*>(scm + 16384 + e0) = l2;
                split2(v[2], v[3], h2, l2);
                *reinterpret_cast<__nv_bfloat162*>(scm + e1) = h2;
                *reinterpret_cast<__nv_bfloat162*>(scm + 16384 + e1) = l2;
            }
        __syncthreads();
        int grp = n0g >> 8, lc0 = n0g & 255;
        __nv_bfloat16* OH = grp == 0 ? Oh : (grp == 1 ? Oh1 : Oh2);
        __nv_bfloat16* OL = grp == 0 ? Ol : (grp == 1 ? Ol1 : Ol2);
        const int nchO = (Nfull >= 256 ? 4 : (Nfull >> 6));
        size_t baseB = (((size_t)mt * nchO + (lc0 >> 6)) * 8192) * 2;
        char* dH = (char*)OH + baseB;
        char* dL = (char*)OL + baseB;
        for (int i = tid * 16; i < 16384; i += NT * 16) {
            *reinterpret_cast<float4*>(dH + i) =
                *reinterpret_cast<const float4*>(scm + i);
            *reinterpret_cast<float4*>(dL + i) =
                *reinterpret_cast<const float4*>(scm + 16384 + i);
        }
    } else {
        float* st = (float*)scm;  // row stride 68 floats
#pragma unroll
        for (int mi = 0; mi < 2; mi++)
#pragma unroll
            for (int nj = 0; nj < 4; nj++) {
                int lc = n0l + nj * 8 + cq;
                int cg = n0g + lc;
                float b0 = g_Ba[boz + cg], b1 = g_Ba[boz + cg + 1];
                float v[4] = {acc[mi][nj][0] + b0, acc[mi][nj][1] + b1,
                              acc[mi][nj][2] + b0, acc[mi][nj][3] + b1};
                if (act) {
#pragma unroll
                    for (int q = 0; q < 4; q++)
                        v[q] = v[q] >= 0.f ? v[q] : 0.2f * v[q];
                }
                int r0 = m0 + mi * 16 + rq, r1 = r0 + 8;
                st[r0 * 68 + lc] = v[0];
                st[r0 * 68 + lc + 1] = v[1];
                st[r1 * 68 + lc] = v[2];
                st[r1 * 68 + lc + 1] = v[3];
            }
        __syncthreads();
        size_t m0r = (size_t)mt * 128;
        for (int idx = tid; idx < 2048; idx += NT) {
            int row = idx >> 4, qq = idx & 15;
            float4 vv = *reinterpret_cast<const float4*>(st + row * 68 + qq * 4);
            *reinterpret_cast<float4*>(Ofz + (m0r + row) * Nfull + n0g + qq * 4) = vv;
        }
    }
}

// ---------------- agg in h2-space: G_n = sum_m h2_m - h2_n (pair images) ---
__global__ __launch_bounds__(128) void agg2_k(const __nv_bfloat16* __restrict__ S2h,
                                              const __nv_bfloat16* __restrict__ S2l,
                                              __nv_bfloat16* __restrict__ Gh,
                                              __nv_bfloat16* __restrict__ Gl) {
    int b = blockIdx.x, p = threadIdx.x;
    int chunk = p >> 5, cc = (2 * p) & 63;
    float2 v[NN];
    float sx = 0.f, sy = 0.f;
    size_t eo[NN];
#pragma unroll
    for (int n = 0; n < NN; n++) {
        size_t m = (size_t)b * NN + n;
        size_t tile = m >> 7; int rt = (int)(m & 127);
        size_t e = (tile * 4 + chunk) * 8192 + (SWZ(rt * 128 + cc * 2) >> 1);
        eo[n] = e;
        __nv_bfloat162 h2 = *reinterpret_cast<const __nv_bfloat162*>(S2h + e);
        __nv_bfloat162 l2 = *reinterpret_cast<const __nv_bfloat162*>(S2l + e);
        v[n] = make_float2(__bfloat162float(h2.x) + __bfloat162float(l2.x),
                           __bfloat162float(h2.y) + __bfloat162float(l2.y));
        sx += v[n].x; sy += v[n].y;
    }
#pragma unroll
    for (int n = 0; n < NN; n++) {
        __nv_bfloat162 h2, l2;
        split2(sx - v[n].x, sy - v[n].y, h2, l2);
        *reinterpret_cast<__nv_bfloat162*>(Gh + eo[n]) = h2;
        *reinterpret_cast<__nv_bfloat162*>(Gl + eo[n]) = l2;
    }
}

// ---------------- attention per batch (fp32), ctx -> swz bf16 pair
#define ATT_FLOATS (5888 + 6144 + 5888 + 4416)
__global__ __launch_bounds__(NT) void att_k(const float* __restrict__ QH,
                                            const float* __restrict__ KH,
                                            const float* __restrict__ VH,
                                            __nv_bfloat16* __restrict__ CXh,
                                            __nv_bfloat16* __restrict__ CXl) {
    extern __shared__ float sm[];
    float* q = sm;
    float* kT = q + 5888;
    float* v = kT + 6144;
    float* S = v + 5888;
    const int tid = threadIdx.x, b = blockIdx.x;
    const size_t base = (size_t)b * NN * 256;

    for (int i = tid; i < 1472; i += NT) {
        reinterpret_cast<float4*>(q)[i] = reinterpret_cast<const float4*>(QH + base)[i];
        reinterpret_cast<float4*>(v)[i] = reinterpret_cast<const float4*>(VH + base)[i];
    }
    for (int i = tid; i < 5888; i += NT) {
        int m = i >> 8, c = i & 255;
        kT[c * 24 + m] = KH[base + (size_t)m * 256 + c];
    }
    __syncthreads();

    int w = tid >> 5, lane = tid & 31;
    for (int task = w; task < 184; task += 8) {
        int h = task / 23, n = task - h * 23;
        const float* qr = q + n * 256 + h * 32;
        float a = 0.f;
        if (lane < NN) {
#pragma unroll
            for (int d = 0; d < 32; d++) a += qr[d] * kT[(h * 32 + d) * 24 + lane];
        }
        float mx = (lane < NN) ? a : -1e30f;
#pragma unroll
        for (int o = 16; o; o >>= 1) mx = fmaxf(mx, __shfl_xor_sync(~0u, mx, o));
        float e = (lane < NN) ? __expf(a - mx) : 0.f;
        float s = e;
#pragma unroll
        for (int o = 16; o; o >>= 1) s += __shfl_xor_sync(~0u, s, o);
        if (lane < NN) S[h * 552 + n * 24 + lane] = e / s;
    }
    __syncthreads();

    for (int idx = tid; idx < NN * 128; idx += NT) {
        int n = idx >> 7, p = idx & 127, h = p >> 4;
        const float* Sr = S + h * 552 + n * 24;
        const float* vc = v + 2 * p;
        float ax = 0.f, ay = 0.f;
#pragma unroll
        for (int m = 0; m < NN; m++) {
            float s = Sr[m];
            ax += s * vc[m * 256];
            ay += s * vc[m * 256 + 1];
        }
        size_t mr = (size_t)b * NN + n;
        size_t tile = mr >> 7; int rt = (int)(mr & 127);
        size_t e = (tile * 4 + (p >> 5)) * 8192 + (SWZ(rt * 128 + ((2 * p) & 63) * 2) >> 1);
        __nv_bfloat162 h2, l2;
        split2(ax, ay, h2, l2);
        *reinterpret_cast<__nv_bfloat162*>(CXh + e) = h2;
        *reinterpret_cast<__nv_bfloat162*>(CXl + e) = l2;
    }
}

// ---------------- maxpool over nodes
__global__ __launch_bounds__(128) void pool_k(const float* __restrict__ CT2,
                                              __nv_bfloat16* __restrict__ PLh,
                                              __nv_bfloat16* __restrict__ PLl) {
    int b = blockIdx.x, p = threadIdx.x;
    float mx = -1e30f, my = -1e30f;
#pragma unroll
    for (int n = 0; n < NN; n++) {
        float2 t = *reinterpret_cast<const float2*>(CT2 + ((size_t)b * NN + n) * 256 + 2 * p);
        mx = fmaxf(mx, t.x); my = fmaxf(my, t.y);
    }
    size_t tile = b >> 7; int rt = b & 127;
    size_t e = (tile * 4 + (p >> 5)) * 8192 + (SWZ(rt * 128 + ((2 * p) & 63) * 2) >> 1);
    __nv_bfloat162 h2, l2;
    split2(mx, my, h2, l2);
    *reinterpret_cast<__nv_bfloat162*>(PLh + e) = h2;
    *reinterpret_cast<__nv_bfloat162*>(PLl + e) = l2;
}

// ---------------- head3: [B,64] -> [B,2]
__global__ __launch_bounds__(NT) void head3_k(const float* __restrict__ H2,
                                              float* __restrict__ out) {
    int b = blockIdx.x * NT + threadIdx.x;
    if (b >= BSZ) return;
    const float* h = H2 + (size_t)b * 64;
    float a0 = g_Ba[B3HO], a1 = g_Ba[B3HO + 1];
#pragma unroll
    for (int k = 0; k < 64; k++) {
        float x = h[k];
        a0 += x * g_Ba[W3HO + k];
        a1 += x * g_Ba[W3HO + 64 + k];
    }
    out[b * 2] = a0;
    out[b * 2 + 1] = a1;
}

// ---------------------------------------------------------------------------
extern "C" void kernel_launch(void* const* d_in, const int* in_sizes, int n_in,
                              void* d_out, int out_size) {
    const float* x   = (const float*)d_in[0];
    const float* mw1 = (const float*)d_in[1];
    const float* mb1 = (const float*)d_in[2];
    const float* mw2 = (const float*)d_in[3];
    const float* mb2 = (const float*)d_in[4];
    const float* mw3 = (const float*)d_in[5];
    const float* mb3 = (const float*)d_in[6];
    const float* qw  = (const float*)d_in[7];
    const float* qb  = (const float*)d_in[8];
    const float* kw  = (const float*)d_in[9];
    const float* kb  = (const float*)d_in[10];
    const float* vw  = (const float*)d_in[11];
    const float* vb  = (const float*)d_in[12];
    const float* inw = (const float*)d_in[13];
    const float* inb = (const float*)d_in[14];
    const float* ow  = (const float*)d_in[15];
    const float* ob  = (const float*)d_in[16];
    const float* ow1 = (const float*)d_in[17];
    const float* ob1 = (const float*)d_in[18];
    const float* ow2 = (const float*)d_in[19];
    const float* ob2 = (const float*)d_in[20];
    const float* ow3 = (const float*)d_in[21];
    const float* ob3 = (const float*)d_in[22];
    float* out = (float*)d_out;
    const float s = 0.17677669529663687f;

    char *R0, *R1, *R2, *R3, *RS;
    cudaGetSymbolAddress((void**)&R0, g_R0);
    cudaGetSymbolAddress((void**)&R1, g_R1);
    cudaGetSymbolAddress((void**)&R2, g_R2);
    cudaGetSymbolAddress((void**)&R3, g_R3);
    cudaGetSymbolAddress((void**)&RS, g_RS);

    typedef __nv_bfloat16 bf;
    const size_t E64 = (size_t)MTOT * 64, E128 = (size_t)MTOT * 128,
                 E256 = (size_t)MTOT * 256;
    bf *XAh = (bf*)R0, *XAl = XAh + E64;
    bf *S1h = (bf*)R1, *S1l = S1h + E128;
    bf *S2h = (bf*)R2, *S2l = S2h + E256;
    bf *Gh  = (bf*)R0, *Gl  = Gh + E256;      // XA dead
    bf *Tqh = (bf*)R1, *Tql = Tqh + E256;     // S1 dead
    bf *Tkh = (bf*)R2, *Tkl = Tkh + E256;     // S2 dead (after agg2)
    bf *Tvh = (bf*)R3, *Tvl = Tvh + E256;
    float *QH = (float*)R0;                   // G dead
    float *KH = (float*)R1;                   // Tq dead
    float *VH = (float*)R2;                   // Tk dead
    bf *CXh = (bf*)R3, *CXl = CXh + E256;     // Tv dead
    float *CT2 = (float*)R0;                  // QH dead
    bf *PLh = (bf*)(RS + RS_PLH), *PLl = (bf*)(RS + RS_PLL);
    bf *H1h = (bf*)(RS + RS_H1H), *H1l = (bf*)(RS + RS_H1L);
    float *H2 = (float*)(RS + RS_H2);
    float *scr = (float*)R3;                  // fold scratch (prep-time only)

    // ---- prep: fold W3 into QKV, pack weights/biases, pack x ----
    fold_k<<<dim3(256, 3), 256>>>(qw, kw, vw, mw3, scr);
    fold_b<<<3, 256>>>(qw, kw, vw, qb, kb, vb, mb3);
    PrepAll pa;
    const float* srcs[9] = {mw1, mw2, scr, inw, inw + 65536, inw + 131072,
                            ow, ow1, ow2};
    int Os[9]   = {128, 256, 768, 256, 256, 256, 256, 128, 64};
    int Ks[9]   = {7, 128, 256, 256, 256, 256, 256, 256, 128};
    int nchs[9] = {1, 2, 4, 4, 4, 4, 4, 4, 2};
    float scs[9] = {1.f, 1.f, 1.f, s, 1.f, 1.f, 1.f, 1.f, 1.f};
    int offs[9] = {W1OFF, W2OFF, FQOFF, WQOFF, WKOFF, WVOFF, OWOFF, O1OFF, O2OFF};
    for (int i = 0; i < 9; i++) {
        pa.src[i] = srcs[i]; pa.O[i] = Os[i]; pa.K[i] = Ks[i];
        pa.nch[i] = nchs[i]; pa.scale[i] = scs[i]; pa.off[i] = offs[i];
    }
    prep_w_all<<<dim3(64, 9), 256>>>(pa);
    prep_bias<<<1, 256>>>(mb1, mb2, inb, ob, ob1, ob2, ow3, ob3);
    prep_x<<<512, 256>>>(x, XAh, XAl);

    cudaFuncSetAttribute(gemm_hmma,
                         cudaFuncAttributeMaxDynamicSharedMemorySize, GSMEM);
    cudaFuncSetAttribute(att_k, cudaFuncAttributeMaxDynamicSharedMemorySize,
                         ATT_FLOATS * 4);

    const int MT = MTOT / 128;  // 2944
    dim3 G128(2, MT), G256(4, MT), G768(12, MT), GIP(4, MT, 3),
         GH1(2, BSZ / 128), GH2(1, BSZ / 128);
    bf* Z = nullptr;
    float* F0 = nullptr;

    gemm_hmma<<<G128, NT, GSMEM>>>(XAh, XAl, Z, Z, Z, Z, 1, W1OFF, 0, 128,
                                   B1O, 1, 0, S1h, S1l, Z, Z, Z, Z, F0, F0, F0);
    gemm_hmma<<<G256, NT, GSMEM>>>(S1h, S1l, Z, Z, Z, Z, 2, W2OFF, 0, 256,
                                   B2O, 1, 0, S2h, S2l, Z, Z, Z, Z, F0, F0, F0);
    agg2_k<<<BSZ, 128>>>(S2h, S2l, Gh, Gl);
    gemm_hmma<<<G768, NT, GSMEM>>>(Gh, Gl, Z, Z, Z, Z, 4, FQOFF, 0, 768,
                                   FQB, 1, 0, Tqh, Tql, Tkh, Tkl, Tvh, Tvl,
                                   F0, F0, F0);
    gemm_hmma<<<GIP, NT, GSMEM>>>(Tqh, Tql, Tkh, Tkl, Tvh, Tvl, 4, WQOFF,
                                  65536, 256, BQO, 0, 1, Z, Z, Z, Z, Z, Z,
                                  QH, KH, VH);
    att_k<<<BSZ, NT, ATT_FLOATS * 4>>>(QH, KH, VH, CXh, CXl);
    gemm_hmma<<<G256, NT, GSMEM>>>(CXh, CXl, Z, Z, Z, Z, 4, OWOFF, 0, 256,
                                   OBO, 0, 1, Z, Z, Z, Z, Z, Z, CT2, F0, F0);
    pool_k<<<BSZ, 128>>>(CT2, PLh, PLl);
    gemm_hmma<<<GH1, NT, GSMEM>>>(PLh, PLl, Z, Z, Z, Z, 4, O1OFF, 0, 128,
                                  OB1O, 1, 0, H1h, H1l, Z, Z, Z, Z, F0, F0, F0);
    gemm_hmma<<<GH2, NT, GSMEM>>>(H1h, H1l, Z, Z, Z, Z, 2, O2OFF, 0, 64,
                                  OB2O, 1, 1, Z, Z, Z, Z, Z, Z, H2, F0, F0);
    head3_k<<<BSZ / NT, NT>>>(H2, out);
}